// round 14
// baseline (speedup 1.0000x reference)
#include <cuda_runtime.h>
#include <cuda_bf16.h>
#include <cstdint>
#include <math.h>

// Problem constants
#define Bq   4
#define Tq   4096
#define Hh   8
#define Dd   32
#define HIDq 512
#define NC   1040            // packed projection columns: q256 k256 v256 w256 beta8 g8
#define NCP  1152            // NC padded to multiple of 128
#define MROWS (Bq*Tq)        // 16384
#define BH   (Bq*Hh)         // 32
#define CCH  64              // chunks
#define LCH  64              // steps per chunk
#define WPB  4               // warps per block in scan kernels

// -------------------- scratch (device globals; zero-initialized, no allocation) ----
__device__ float          g_Y[(size_t)MROWS * NC];        // projection output (68 MB)
__device__ __nv_bfloat16  g_Wh[(size_t)NCP * HIDq];       // packed weights hi (pad rows zero)
__device__ __nv_bfloat16  g_Wl[(size_t)NCP * HIDq];       // packed weights lo
__device__ __nv_bfloat16  g_xh[(size_t)MROWS * HIDq];     // x hi (16 MB)
__device__ __nv_bfloat16  g_xl[(size_t)MROWS * HIDq];     // x lo
__device__ __nv_bfloat16  g_woh[(size_t)HIDq * 256];      // Wo hi
__device__ __nv_bfloat16  g_wol[(size_t)HIDq * 256];      // Wo lo
__device__ __nv_bfloat16  g_atth[(size_t)MROWS * 256];    // attention out hi (8 MB)
__device__ __nv_bfloat16  g_attl[(size_t)MROWS * 256];    // attention out lo
__device__ float  g_w[(size_t)BH * Tq * Dd];              // normalized w (SoA streams)
__device__ float  g_v[(size_t)BH * Tq * Dd];
__device__ float  g_k[(size_t)BH * Tq * Dd];
__device__ float  g_q[(size_t)BH * Tq * Dd];              // q*scale*eg
__device__ float  g_beta[(size_t)BH * Tq];                // beta
__device__ float  g_P [(size_t)BH * CCH * 1024];          // chunk transfer matrices
__device__ float  g_A [(size_t)BH * CCH * 1024];          // chunk injections
__device__ float  g_S0[(size_t)BH * CCH * 1024];          // state at chunk starts

// -------------------- helpers --------------------
__device__ __forceinline__ void bf16split(float v, __nv_bfloat16& hi, __nv_bfloat16& lo) {
    hi = __float2bfloat16(v);
    lo = __float2bfloat16(v - __bfloat162float(hi));
}

__device__ __forceinline__ void ldsm4(uint32_t& r0, uint32_t& r1, uint32_t& r2, uint32_t& r3,
                                      uint32_t addr) {
    asm volatile("ldmatrix.sync.aligned.m8n8.x4.shared.b16 {%0,%1,%2,%3}, [%4];"
        : "=r"(r0), "=r"(r1), "=r"(r2), "=r"(r3) : "r"(addr));
}

__device__ __forceinline__ void mma_bf16(float* d, uint32_t a0, uint32_t a1, uint32_t a2,
                                         uint32_t a3, uint32_t b0, uint32_t b1) {
    asm volatile("mma.sync.aligned.m16n8k16.row.col.f32.bf16.bf16.f32 "
        "{%0,%1,%2,%3}, {%4,%5,%6,%7}, {%8,%9}, {%0,%1,%2,%3};"
        : "+f"(d[0]), "+f"(d[1]), "+f"(d[2]), "+f"(d[3])
        : "r"(a0), "r"(a1), "r"(a2), "r"(a3), "r"(b0), "r"(b1));
}

// swizzled smem byte offset within one 128x32 bf16 array: row stride 64B, 4 chunks of 16B
__device__ __forceinline__ uint32_t swz(int row, int col) {
    uint32_t chunk = (uint32_t)(col >> 3);
    return (uint32_t)(row * 64) + ((chunk ^ (((uint32_t)row >> 1) & 3u)) << 4);
}

__device__ __forceinline__ uint32_t s2u(const void* p) {
    return (uint32_t)__cvta_generic_to_shared(p);
}

// -------------------- fused conversions: pack/split W, split x, split Wo ------------
// blockIdx ranges: [0,2080) packW, [2080,10272) cvtA, [10272,10784) cvtWo
__global__ void __launch_bounds__(256) cvtAll(
        const float* __restrict__ x,
        const float* __restrict__ wq, const float* __restrict__ wk,
        const float* __restrict__ wv, const float* __restrict__ ww,
        const float* __restrict__ wb, const float* __restrict__ wg,
        const float* __restrict__ Wo) {
    int b = blockIdx.x;
    if (b < 2080) {
        int i = b * 256 + threadIdx.x;           // 0 .. 532479
        int r = i >> 9, c = i & 511;
        float v;
        if      (r < 256)  v = wq[i];
        else if (r < 512)  v = wk[(r - 256)  * HIDq + c];
        else if (r < 768)  v = wv[(r - 512)  * HIDq + c];
        else if (r < 1024) v = ww[(r - 768)  * HIDq + c];
        else if (r < 1032) v = wb[(r - 1024) * HIDq + c];
        else               v = wg[(r - 1032) * HIDq + c];
        __nv_bfloat16 hi, lo;
        bf16split(v, hi, lo);
        g_Wh[i] = hi; g_Wl[i] = lo;
    } else if (b < 10272) {
        int i = (b - 2080) * 256 + threadIdx.x;  // float4 index, 2097152 total
        float4 v = ((const float4*)x)[i];
        __nv_bfloat16 h0, l0, h1, l1, h2, l2, h3, l3;
        bf16split(v.x, h0, l0); bf16split(v.y, h1, l1);
        bf16split(v.z, h2, l2); bf16split(v.w, h3, l3);
        ((__nv_bfloat162*)g_xh)[2*i]   = __halves2bfloat162(h0, h1);
        ((__nv_bfloat162*)g_xh)[2*i+1] = __halves2bfloat162(h2, h3);
        ((__nv_bfloat162*)g_xl)[2*i]   = __halves2bfloat162(l0, l1);
        ((__nv_bfloat162*)g_xl)[2*i+1] = __halves2bfloat162(l2, l3);
    } else {
        int i = (b - 10272) * 256 + threadIdx.x; // 0 .. 131071
        __nv_bfloat16 hi, lo;
        bf16split(Wo[i], hi, lo);
        g_woh[i] = hi; g_wol[i] = lo;
    }
}

// -------------------- tensor-core GEMM: C[M,Nreal] = A[M,K] * B[N,K]^T --------------
// 3-term bf16 split, 128x128x32 tiles, 8 warps, 64x32 warp tiles, 3-stage swizzled
// cp.async ring, 2 CTAs/SM. Warps whose entire column range is padding skip compute.
__global__ void __launch_bounds__(256, 2)
hgemm3(const __nv_bfloat16* __restrict__ Ahp, const __nv_bfloat16* __restrict__ Alp,
       const __nv_bfloat16* __restrict__ Bhp, const __nv_bfloat16* __restrict__ Blp,
       float* __restrict__ C, int M, int Nreal, int K, int epi,
       const float* __restrict__ bbeta, const float* __restrict__ bg) {
    extern __shared__ __nv_bfloat16 smem[];   // 3 stages * 4 arrays * 128*32 bf16 = 96KB
    const int tid  = threadIdx.x;
    const int wid  = tid >> 5, lane = tid & 31;
    const int m0 = blockIdx.y * 128, n0 = blockIdx.x * 128;
    const int wm = (wid >> 2) * 64, wn = (wid & 3) * 32;
    const bool active = (n0 + wn) < Nreal;
    const uint32_t sbase = s2u(&smem[0]);

    const __nv_bfloat16* gsrc[4];
    gsrc[0] = Ahp + (size_t)m0 * K;
    gsrc[1] = Alp + (size_t)m0 * K;
    gsrc[2] = Bhp + (size_t)n0 * K;
    gsrc[3] = Blp + (size_t)n0 * K;

    float acc[4][4][4];
#pragma unroll
    for (int mi = 0; mi < 4; ++mi)
#pragma unroll
        for (int nj = 0; nj < 4; ++nj)
#pragma unroll
            for (int cc = 0; cc < 4; ++cc) acc[mi][nj][cc] = 0.f;

    auto load_stage = [&](int s, int kt) {
#pragma unroll
        for (int arr = 0; arr < 4; ++arr) {
            uint32_t abase = sbase + (uint32_t)s * 32768u + (uint32_t)arr * 8192u;
            const __nv_bfloat16* src = gsrc[arr];
#pragma unroll
            for (int i = 0; i < 2; ++i) {
                int lin = i * 256 + tid;
                int r = lin >> 2, c = lin & 3;
                uint32_t dst = abase + swz(r, c * 8);
                const void* sp = src + (size_t)r * K + kt + c * 8;
                asm volatile("cp.async.cg.shared.global [%0], [%1], 16;" :: "r"(dst), "l"(sp));
            }
        }
        asm volatile("cp.async.commit_group;");
    };

    const int KT = K / 32;
    load_stage(0, 0);
    if (KT > 1) load_stage(1, 32);

    for (int it = 0; it < KT; ++it) {
        if (it + 1 < KT) {
            asm volatile("cp.async.wait_group 1;");
        } else {
            asm volatile("cp.async.wait_group 0;");
        }
        __syncthreads();   // single barrier: stage it%3 visible AND iter it-1 reads done
        if (it + 2 < KT) load_stage((it + 2) % 3, (it + 2) * 32);

        if (active) {
            const uint32_t stg = sbase + (uint32_t)(it % 3) * 32768u;
            const uint32_t aHs = stg;
            const uint32_t aLs = stg + 8192u;
            const uint32_t bHs = stg + 16384u;
            const uint32_t bLs = stg + 24576u;

#pragma unroll
            for (int kk = 0; kk < 32; kk += 16) {
                uint32_t fbh[4][2], fbl[4][2];
#pragma unroll
                for (int j = 0; j < 2; ++j) {
                    int row = wn + j * 16 + (lane & 7) + ((lane >> 4) & 1) * 8;
                    int col = kk + ((lane >> 3) & 1) * 8;
                    uint32_t off = swz(row, col);
                    uint32_t t0, t1, t2, t3;
                    ldsm4(t0, t1, t2, t3, bHs + off);
                    fbh[j*2][0] = t0; fbh[j*2][1] = t1; fbh[j*2+1][0] = t2; fbh[j*2+1][1] = t3;
                    ldsm4(t0, t1, t2, t3, bLs + off);
                    fbl[j*2][0] = t0; fbl[j*2][1] = t1; fbl[j*2+1][0] = t2; fbl[j*2+1][1] = t3;
                }
#pragma unroll
                for (int mi = 0; mi < 4; ++mi) {
                    int row = wm + mi * 16 + (lane & 7) + ((lane >> 3) & 1) * 8;
                    int col = kk + ((lane >> 4) & 1) * 8;
                    uint32_t off = swz(row, col);
                    uint32_t ah0, ah1, ah2, ah3, al0, al1, al2, al3;
                    ldsm4(ah0, ah1, ah2, ah3, aHs + off);
                    ldsm4(al0, al1, al2, al3, aLs + off);
#pragma unroll
                    for (int nj = 0; nj < 4; ++nj)
                        mma_bf16(acc[mi][nj], ah0, ah1, ah2, ah3, fbh[nj][0], fbh[nj][1]);
#pragma unroll
                    for (int nj = 0; nj < 4; ++nj)
                        mma_bf16(acc[mi][nj], ah0, ah1, ah2, ah3, fbl[nj][0], fbl[nj][1]);
#pragma unroll
                    for (int nj = 0; nj < 4; ++nj)
                        mma_bf16(acc[mi][nj], al0, al1, al2, al3, fbh[nj][0], fbh[nj][1]);
                }
            }
        }
    }

    const int grp = lane >> 2, t2c = (lane & 3) << 1;
#pragma unroll
    for (int mi = 0; mi < 4; ++mi) {
#pragma unroll
        for (int nj = 0; nj < 4; ++nj) {
            int gm = m0 + wm + mi * 16 + grp;
            int gn = n0 + wn + nj * 8 + t2c;
            if (gn < Nreal) {
                float v0 = acc[mi][nj][0], v1 = acc[mi][nj][1];
                float v2 = acc[mi][nj][2], v3 = acc[mi][nj][3];
                if (epi && gn >= 1024) {
                    if (gn < 1032) {
                        v0 = 2.f / (1.f + expf(-(v0 + bbeta[gn - 1024])));
                        v1 = 2.f / (1.f + expf(-(v1 + bbeta[gn - 1023])));
                        v2 = 2.f / (1.f + expf(-(v2 + bbeta[gn - 1024])));
                        v3 = 2.f / (1.f + expf(-(v3 + bbeta[gn - 1023])));
                    } else {
                        v0 = 1.f / (1.f + expf(-(v0 + bg[gn - 1032])));
                        v1 = 1.f / (1.f + expf(-(v1 + bg[gn - 1031])));
                        v2 = 1.f / (1.f + expf(-(v2 + bg[gn - 1032])));
                        v3 = 1.f / (1.f + expf(-(v3 + bg[gn - 1031])));
                    }
                }
                float* p0 = C + (size_t)gm * Nreal + gn;
                float* p1 = C + (size_t)(gm + 8) * Nreal + gn;
                p0[0] = v0; p0[1] = v1;
                p1[0] = v2; p1[1] = v3;
            }
        }
    }
}

// -------------------- prep: normalize w, fold q*scale*eg, SoA streams ---------------
__global__ void __launch_bounds__(256) prep() {
    const float scale = 0.17677669529663687f;   // 32^-0.5
    int g    = blockIdx.x * 8 + (threadIdx.x >> 5);
    int lane = threadIdx.x & 31;
    int bh = g >> 12;
    int t  = g & 4095;
    int b = bh >> 3, h = bh & 7;
    const float* r = g_Y + (size_t)(b * Tq + t) * NC;

    float w = r[768 + h * 32 + lane];
    float ss = w * w;
    ss += __shfl_xor_sync(0xffffffffu, ss, 16);
    ss += __shfl_xor_sync(0xffffffffu, ss, 8);
    ss += __shfl_xor_sync(0xffffffffu, ss, 4);
    ss += __shfl_xor_sync(0xffffffffu, ss, 2);
    ss += __shfl_xor_sync(0xffffffffu, ss, 1);
    w = w / (sqrtf(ss) + 1e-6f);

    float v    = r[512 + h * 32 + lane];
    float k    = r[256 + h * 32 + lane];
    float q    = r[       h * 32 + lane];
    float beta = r[1024 + h];
    float eg   = r[1032 + h];   // sigmoid(zg) == exp(log_sigmoid(zg))

    size_t o = (size_t)g * 32 + lane;
    g_w[o] = w; g_v[o] = v; g_k[o] = k; g_q[o] = q * scale * eg;
    if (lane == 0) g_beta[g] = beta;
}

// -------------------- pass1: per-chunk transfer matrix P and injection A --------------------
// cp.async triple-buffered SoA windows (prefetch distance 2).
__global__ void __launch_bounds__(WPB*32) scanPA() {
    __shared__ float wbuf[WPB][3][8][32];
    __shared__ float vbuf[WPB][3][8][32];
    __shared__ float kbuf[WPB][3][8][32];
    __shared__ float bbuf[WPB][3][8];

    const int wid  = threadIdx.x >> 5;
    const int lane = threadIdx.x & 31;
    const int wg   = blockIdx.x * WPB + wid;
    const int bh   = wg >> 6;
    const int c    = wg & 63;
    const size_t sbase = ((size_t)bh * Tq + (size_t)c * LCH) * 32;
    const size_t bbase = (size_t)bh * Tq + (size_t)c * LCH;

    auto issue = [&](int wnd, int bf) {
        size_t goff = sbase + (size_t)wnd * 256;
        uint32_t dw = s2u(&wbuf[wid][bf][0][0]);
        uint32_t dv = s2u(&vbuf[wid][bf][0][0]);
        uint32_t dk = s2u(&kbuf[wid][bf][0][0]);
#pragma unroll
        for (int i = 0; i < 2; ++i) {
            int e4 = i * 32 + lane;
            const void* sw = (const float4*)(g_w + goff) + e4;
            const void* sv = (const float4*)(g_v + goff) + e4;
            const void* sk = (const float4*)(g_k + goff) + e4;
            asm volatile("cp.async.cg.shared.global [%0], [%1], 16;" :: "r"(dw + e4*16u), "l"(sw));
            asm volatile("cp.async.cg.shared.global [%0], [%1], 16;" :: "r"(dv + e4*16u), "l"(sv));
            asm volatile("cp.async.cg.shared.global [%0], [%1], 16;" :: "r"(dk + e4*16u), "l"(sk));
        }
        if (lane < 8) {
            uint32_t db = s2u(&bbuf[wid][bf][lane]);
            asm volatile("cp.async.ca.shared.global [%0], [%1], 4;"
                         :: "r"(db), "l"(g_beta + bbase + wnd * 8 + lane));
        }
        asm volatile("cp.async.commit_group;");
    };

    issue(0, 0);
    issue(1, 1);
    issue(2, 2);
    asm volatile("cp.async.wait_group 2;" ::: "memory");
    __syncwarp();

    float P[32], A[32];
#pragma unroll
    for (int m = 0; m < 32; ++m) { P[m] = (m == lane) ? 1.f : 0.f; A[m] = 0.f; }

    for (int w = 0; w < 8; ++w) {
        const int cur = w % 3;
#pragma unroll
        for (int t = 0; t < 8; ++t) {
            const float4* w4p = (const float4*)&wbuf[wid][cur][t][0];
            const float4* v4p = (const float4*)&vbuf[wid][cur][t][0];
            float k    = kbuf[wid][cur][t][lane];
            float beta = bbuf[wid][cur][t];
            float p0 = 0.f, p1 = 0.f, p2 = 0.f, p3 = 0.f;
            float a0 = 0.f, a1 = 0.f, a2 = 0.f, a3 = 0.f;
            float4 w4[8];
#pragma unroll
            for (int j = 0; j < 8; ++j) {
                w4[j] = w4p[j];
                p0 = fmaf(P[4*j+0], w4[j].x, p0);
                p1 = fmaf(P[4*j+1], w4[j].y, p1);
                p2 = fmaf(P[4*j+2], w4[j].z, p2);
                p3 = fmaf(P[4*j+3], w4[j].w, p3);
                a0 = fmaf(A[4*j+0], w4[j].x, a0);
                a1 = fmaf(A[4*j+1], w4[j].y, a1);
                a2 = fmaf(A[4*j+2], w4[j].z, a2);
                a3 = fmaf(A[4*j+3], w4[j].w, a3);
            }
            float cp = -beta * ((p0 + p1) + (p2 + p3));
            float ca = -beta * ((a0 + a1) + (a2 + a3));
#pragma unroll
            for (int j = 0; j < 8; ++j) {
                float4 v4 = v4p[j];
                P[4*j+0] = fmaf(cp, w4[j].x, P[4*j+0]);
                P[4*j+1] = fmaf(cp, w4[j].y, P[4*j+1]);
                P[4*j+2] = fmaf(cp, w4[j].z, P[4*j+2]);
                P[4*j+3] = fmaf(cp, w4[j].w, P[4*j+3]);
                A[4*j+0] = fmaf(ca, w4[j].x, fmaf(k, v4.x, A[4*j+0]));
                A[4*j+1] = fmaf(ca, w4[j].y, fmaf(k, v4.y, A[4*j+1]));
                A[4*j+2] = fmaf(ca, w4[j].z, fmaf(k, v4.z, A[4*j+2]));
                A[4*j+3] = fmaf(ca, w4[j].w, fmaf(k, v4.w, A[4*j+3]));
            }
        }
        __syncwarp();
        if (w + 3 < 8) {
            issue(w + 3, cur);
            asm volatile("cp.async.wait_group 2;" ::: "memory");
        } else if (w == 5) {
            asm volatile("cp.async.wait_group 1;" ::: "memory");
        } else if (w == 6) {
            asm volatile("cp.async.wait_group 0;" ::: "memory");
        }
        __syncwarp();
    }

    size_t obase = ((size_t)bh * CCH + c) * 1024 + (size_t)lane * 32;
#pragma unroll
    for (int j = 0; j < 8; ++j) {
        *(float4*)&g_P[obase + 4*j] = make_float4(P[4*j], P[4*j+1], P[4*j+2], P[4*j+3]);
        *(float4*)&g_A[obase + 4*j] = make_float4(A[4*j], A[4*j+1], A[4*j+2], A[4*j+3]);
    }
}

// -------------------- combine: sequential chunk-boundary states --------------------
__global__ void __launch_bounds__(1024, 1) combine() {
    __shared__ float Ssh[32][32];
    const int bh = blockIdx.x;
    const int tid = threadIdx.x;
    const int d = tid >> 5, m = tid & 31;

    float s = 0.f;
    for (int c = 0; c < CCH; ++c) {
        size_t base = ((size_t)bh * CCH + c) * 1024;
        g_S0[base + tid] = s;
        Ssh[d][m] = s;
        __syncthreads();
        float acc = g_A[base + tid];
        const float* Pc = g_P + base;
#pragma unroll
        for (int mm = 0; mm < 32; ++mm)
            acc = fmaf(Ssh[d][mm], Pc[mm * 32 + m], acc);
        __syncthreads();
        s = acc;
    }
}

// -------------------- pass2: replay chunks, emit outputs as bf16 hi/lo ----------------
// cp.async triple-buffered; dynamic smem (67968 B).
__global__ void __launch_bounds__(WPB*32) scanOut() {
    extern __shared__ float dyn[];
    float (*wbuf)[3][8][32] = (float(*)[3][8][32])(dyn);
    float (*vbuf)[3][8][32] = (float(*)[3][8][32])(dyn + 3072);
    float (*kbuf)[3][8][32] = (float(*)[3][8][32])(dyn + 6144);
    float (*qbuf)[3][8][32] = (float(*)[3][8][32])(dyn + 9216);
    float (*part)[32][36]   = (float(*)[32][36])(dyn + 12288);
    float (*bbuf)[3][8]     = (float(*)[3][8])(dyn + 12288 + WPB*32*36);

    const int wid  = threadIdx.x >> 5;
    const int lane = threadIdx.x & 31;
    const int wg   = blockIdx.x * WPB + wid;
    const int bh   = wg >> 6;
    const int c    = wg & 63;
    const int b = bh >> 3, h = bh & 7;
    const size_t sbase = ((size_t)bh * Tq + (size_t)c * LCH) * 32;
    const size_t bbase = (size_t)bh * Tq + (size_t)c * LCH;
    const size_t s0base = ((size_t)bh * CCH + c) * 1024 + (size_t)lane * 32;
    const int rowbase = b * Tq + c * LCH;

    auto issue = [&](int wnd, int bf) {
        size_t goff = sbase + (size_t)wnd * 256;
        uint32_t dw = s2u(&wbuf[wid][bf][0][0]);
        uint32_t dv = s2u(&vbuf[wid][bf][0][0]);
        uint32_t dk = s2u(&kbuf[wid][bf][0][0]);
        uint32_t dq = s2u(&qbuf[wid][bf][0][0]);
#pragma unroll
        for (int i = 0; i < 2; ++i) {
            int e4 = i * 32 + lane;
            asm volatile("cp.async.cg.shared.global [%0], [%1], 16;"
                         :: "r"(dw + e4*16u), "l"((const float4*)(g_w + goff) + e4));
            asm volatile("cp.async.cg.shared.global [%0], [%1], 16;"
                         :: "r"(dv + e4*16u), "l"((const float4*)(g_v + goff) + e4));
            asm volatile("cp.async.cg.shared.global [%0], [%1], 16;"
                         :: "r"(dk + e4*16u), "l"((const float4*)(g_k + goff) + e4));
            asm volatile("cp.async.cg.shared.global [%0], [%1], 16;"
                         :: "r"(dq + e4*16u), "l"((const float4*)(g_q + goff) + e4));
        }
        if (lane < 8) {
            uint32_t db = s2u(&bbuf[wid][bf][lane]);
            asm volatile("cp.async.ca.shared.global [%0], [%1], 4;"
                         :: "r"(db), "l"(g_beta + bbase + wnd * 8 + lane));
        }
        asm volatile("cp.async.commit_group;");
    };

    issue(0, 0);
    issue(1, 1);
    issue(2, 2);
    asm volatile("cp.async.wait_group 2;" ::: "memory");
    __syncwarp();

    float S[32];
#pragma unroll
    for (int j = 0; j < 8; ++j) {
        float4 s0 = *(const float4*)&g_S0[s0base + 4*j];
        S[4*j] = s0.x; S[4*j+1] = s0.y; S[4*j+2] = s0.z; S[4*j+3] = s0.w;
    }

    for (int w = 0; w < 8; ++w) {
        const int cur = w % 3;
#pragma unroll
        for (int t = 0; t < 8; ++t) {
            const float4* w4p = (const float4*)&wbuf[wid][cur][t][0];
            const float4* v4p = (const float4*)&vbuf[wid][cur][t][0];
            float k    = kbuf[wid][cur][t][lane];
            float q    = qbuf[wid][cur][t][lane];
            float beta = bbuf[wid][cur][t];
            float a0 = 0.f, a1 = 0.f, a2 = 0.f, a3 = 0.f;
            float4 w4[8];
#pragma unroll
            for (int j = 0; j < 8; ++j) {
                w4[j] = w4p[j];
                a0 = fmaf(S[4*j+0], w4[j].x, a0);
                a1 = fmaf(S[4*j+1], w4[j].y, a1);
                a2 = fmaf(S[4*j+2], w4[j].z, a2);
                a3 = fmaf(S[4*j+3], w4[j].w, a3);
            }
            float cs = -beta * ((a0 + a1) + (a2 + a3));
#pragma unroll
            for (int j = 0; j < 8; ++j) {
                float4 v4 = v4p[j];
                S[4*j+0] = fmaf(cs, w4[j].x, fmaf(k, v4.x, S[4*j+0]));
                S[4*j+1] = fmaf(cs, w4[j].y, fmaf(k, v4.y, S[4*j+1]));
                S[4*j+2] = fmaf(cs, w4[j].z, fmaf(k, v4.z, S[4*j+2]));
                S[4*j+3] = fmaf(cs, w4[j].w, fmaf(k, v4.w, S[4*j+3]));
            }
#pragma unroll
            for (int j = 0; j < 8; ++j) {
                *(float4*)&part[wid][lane][4*j] =
                    make_float4(q * S[4*j], q * S[4*j+1], q * S[4*j+2], q * S[4*j+3]);
            }
            __syncwarp();
            float o0 = 0.f, o1 = 0.f, o2 = 0.f, o3 = 0.f;
#pragma unroll
            for (int dd = 0; dd < 32; dd += 4) {
                o0 += part[wid][dd+0][lane];
                o1 += part[wid][dd+1][lane];
                o2 += part[wid][dd+2][lane];
                o3 += part[wid][dd+3][lane];
            }
            float o = (o0 + o1) + (o2 + o3);
            size_t oidx = (size_t)(rowbase + w * 8 + t) * 256 + h * 32 + lane;
            __nv_bfloat16 hi, lo;
            bf16split(o, hi, lo);
            g_atth[oidx] = hi; g_attl[oidx] = lo;
            __syncwarp();
        }
        if (w + 3 < 8) {
            issue(w + 3, cur);
            asm volatile("cp.async.wait_group 2;" ::: "memory");
        } else if (w == 5) {
            asm volatile("cp.async.wait_group 1;" ::: "memory");
        } else if (w == 6) {
            asm volatile("cp.async.wait_group 0;" ::: "memory");
        }
        __syncwarp();
    }
}

// -------------------- launch --------------------
extern "C" void kernel_launch(void* const* d_in, const int* in_sizes, int n_in,
                              void* d_out, int out_size) {
    const float* x     = (const float*)d_in[0];
    const float* Wq    = (const float*)d_in[1];
    const float* Wk    = (const float*)d_in[2];
    const float* Wv    = (const float*)d_in[3];
    const float* Ww    = (const float*)d_in[4];
    const float* Wbeta = (const float*)d_in[5];
    const float* bbeta = (const float*)d_in[6];
    const float* Wg    = (const float*)d_in[7];
    const float* bg    = (const float*)d_in[8];
    const float* Wo    = (const float*)d_in[9];
    float* out = (float*)d_out;

    void *pY, *pXh, *pXl, *pWh, *pWl, *pAh, *pAl, *pWoh, *pWol;
    cudaGetSymbolAddress(&pY,   g_Y);
    cudaGetSymbolAddress(&pXh,  g_xh);
    cudaGetSymbolAddress(&pXl,  g_xl);
    cudaGetSymbolAddress(&pWh,  g_Wh);
    cudaGetSymbolAddress(&pWl,  g_Wl);
    cudaGetSymbolAddress(&pAh,  g_atth);
    cudaGetSymbolAddress(&pAl,  g_attl);
    cudaGetSymbolAddress(&pWoh, g_woh);
    cudaGetSymbolAddress(&pWol, g_wol);

    const int SMEM = 3 * 4 * 128 * 32 * 2;   // 98304 bytes (3 swizzled 32KB stages)
    cudaFuncSetAttribute(hgemm3, cudaFuncAttributeMaxDynamicSharedMemorySize, SMEM);
    const int SCAN_SMEM = (12288 + WPB*32*36 + WPB*3*8) * 4;   // 67968 bytes
    cudaFuncSetAttribute(scanOut, cudaFuncAttributeMaxDynamicSharedMemorySize, SCAN_SMEM);

    // 1) fused conversions: pack/split W, split x, split Wo
    cvtAll<<<10784, 256>>>(x, Wq, Wk, Wv, Ww, Wbeta, Wg, Wo);

    // 2) fused projection GEMM + activations: Y[16384,1040] = x @ W^T (tensor cores)
    hgemm3<<<dim3(NCP / 128, MROWS / 128), 256, SMEM>>>(
        (const __nv_bfloat16*)pXh, (const __nv_bfloat16*)pXl,
        (const __nv_bfloat16*)pWh, (const __nv_bfloat16*)pWl,
        (float*)pY, MROWS, NC, HIDq, 1, bbeta, bg);

    // 3) normalize w, fold scales, pack SoA recurrence streams
    prep<<<16384, 256>>>();

    // 4) chunked associative scan over the recurrence
    scanPA<<<(BH * CCH) / WPB, WPB * 32>>>();
    combine<<<BH, 1024>>>();
    scanOut<<<(BH * CCH) / WPB, WPB * 32, SCAN_SMEM>>>();

    // 5) output projection: out[16384,512] = att @ Wo^T (tensor cores)
    hgemm3<<<dim3(HIDq / 128, MROWS / 128), 256, SMEM>>>(
        (const __nv_bfloat16*)pAh, (const __nv_bfloat16*)pAl,
        (const __nv_bfloat16*)pWoh, (const __nv_bfloat16*)pWol,
        out, MROWS, HIDq, Hh * Dd, 0, nullptr, nullptr);
}

// round 15
// speedup vs baseline: 1.0148x; 1.0148x over previous
#include <cuda_runtime.h>
#include <cuda_bf16.h>
#include <cstdint>
#include <math.h>

// Problem constants
#define Bq   4
#define Tq   4096
#define Hh   8
#define Dd   32
#define HIDq 512
#define NC   1040            // packed projection columns: q256 k256 v256 w256 beta8 g8
#define NCP  1152            // NC padded to multiple of 128
#define MROWS (Bq*Tq)        // 16384
#define BH   (Bq*Hh)         // 32
#define CCH  64              // chunks
#define LCH  64              // steps per chunk
#define WPB  4               // warps per block in scan kernels

// -------------------- scratch (device globals; zero-initialized, no allocation) ----
__device__ float          g_Y[(size_t)MROWS * NC];        // projection output (68 MB)
__device__ __nv_bfloat16  g_Wh[(size_t)NCP * HIDq];       // packed weights hi (pad rows zero)
__device__ __nv_bfloat16  g_Wl[(size_t)NCP * HIDq];       // packed weights lo
__device__ __nv_bfloat16  g_xh[(size_t)MROWS * HIDq];     // x hi (16 MB)
__device__ __nv_bfloat16  g_xl[(size_t)MROWS * HIDq];     // x lo
__device__ __nv_bfloat16  g_woh[(size_t)HIDq * 256];      // Wo hi
__device__ __nv_bfloat16  g_wol[(size_t)HIDq * 256];      // Wo lo
__device__ __nv_bfloat16  g_atth[(size_t)MROWS * 256];    // attention out hi (8 MB)
__device__ __nv_bfloat16  g_attl[(size_t)MROWS * 256];    // attention out lo
__device__ float  g_w[(size_t)BH * Tq * Dd];              // normalized w (SoA streams)
__device__ float  g_v[(size_t)BH * Tq * Dd];
__device__ float  g_k[(size_t)BH * Tq * Dd];
__device__ float  g_q[(size_t)BH * Tq * Dd];              // q*scale*eg
__device__ float  g_beta[(size_t)BH * Tq];                // beta
__device__ float  g_P [(size_t)BH * CCH * 1024];          // chunk transfer matrices
__device__ float  g_A [(size_t)BH * CCH * 1024];          // chunk injections
__device__ float  g_S0[(size_t)BH * CCH * 1024];          // state at chunk starts

// -------------------- helpers --------------------
__device__ __forceinline__ void bf16split(float v, __nv_bfloat16& hi, __nv_bfloat16& lo) {
    hi = __float2bfloat16(v);
    lo = __float2bfloat16(v - __bfloat162float(hi));
}

__device__ __forceinline__ void ldsm4(uint32_t& r0, uint32_t& r1, uint32_t& r2, uint32_t& r3,
                                      uint32_t addr) {
    asm volatile("ldmatrix.sync.aligned.m8n8.x4.shared.b16 {%0,%1,%2,%3}, [%4];"
        : "=r"(r0), "=r"(r1), "=r"(r2), "=r"(r3) : "r"(addr));
}

__device__ __forceinline__ void mma_bf16(float* d, uint32_t a0, uint32_t a1, uint32_t a2,
                                         uint32_t a3, uint32_t b0, uint32_t b1) {
    asm volatile("mma.sync.aligned.m16n8k16.row.col.f32.bf16.bf16.f32 "
        "{%0,%1,%2,%3}, {%4,%5,%6,%7}, {%8,%9}, {%0,%1,%2,%3};"
        : "+f"(d[0]), "+f"(d[1]), "+f"(d[2]), "+f"(d[3])
        : "r"(a0), "r"(a1), "r"(a2), "r"(a3), "r"(b0), "r"(b1));
}

// swizzled smem byte offset within one 128x32 bf16 array: row stride 64B, 4 chunks of 16B
__device__ __forceinline__ uint32_t swz(int row, int col) {
    uint32_t chunk = (uint32_t)(col >> 3);
    return (uint32_t)(row * 64) + ((chunk ^ (((uint32_t)row >> 1) & 3u)) << 4);
}

__device__ __forceinline__ uint32_t s2u(const void* p) {
    return (uint32_t)__cvta_generic_to_shared(p);
}

// -------------------- fused conversions: pack/split W, split x, split Wo ------------
// blockIdx ranges: [0,2080) packW, [2080,10272) cvtA, [10272,10784) cvtWo
__global__ void __launch_bounds__(256) cvtAll(
        const float* __restrict__ x,
        const float* __restrict__ wq, const float* __restrict__ wk,
        const float* __restrict__ wv, const float* __restrict__ ww,
        const float* __restrict__ wb, const float* __restrict__ wg,
        const float* __restrict__ Wo) {
    int b = blockIdx.x;
    if (b < 2080) {
        int i = b * 256 + threadIdx.x;           // 0 .. 532479
        int r = i >> 9, c = i & 511;
        float v;
        if      (r < 256)  v = wq[i];
        else if (r < 512)  v = wk[(r - 256)  * HIDq + c];
        else if (r < 768)  v = wv[(r - 512)  * HIDq + c];
        else if (r < 1024) v = ww[(r - 768)  * HIDq + c];
        else if (r < 1032) v = wb[(r - 1024) * HIDq + c];
        else               v = wg[(r - 1032) * HIDq + c];
        __nv_bfloat16 hi, lo;
        bf16split(v, hi, lo);
        g_Wh[i] = hi; g_Wl[i] = lo;
    } else if (b < 10272) {
        int i = (b - 2080) * 256 + threadIdx.x;  // float4 index, 2097152 total
        float4 v = ((const float4*)x)[i];
        __nv_bfloat16 h0, l0, h1, l1, h2, l2, h3, l3;
        bf16split(v.x, h0, l0); bf16split(v.y, h1, l1);
        bf16split(v.z, h2, l2); bf16split(v.w, h3, l3);
        ((__nv_bfloat162*)g_xh)[2*i]   = __halves2bfloat162(h0, h1);
        ((__nv_bfloat162*)g_xh)[2*i+1] = __halves2bfloat162(h2, h3);
        ((__nv_bfloat162*)g_xl)[2*i]   = __halves2bfloat162(l0, l1);
        ((__nv_bfloat162*)g_xl)[2*i+1] = __halves2bfloat162(l2, l3);
    } else {
        int i = (b - 10272) * 256 + threadIdx.x; // 0 .. 131071
        __nv_bfloat16 hi, lo;
        bf16split(Wo[i], hi, lo);
        g_woh[i] = hi; g_wol[i] = lo;
    }
}

// -------------------- tensor-core GEMM: C[M,Nreal] = A[M,K] * B[N,K]^T --------------
// 3-term bf16 split, 128x128x32 tiles, 8 warps, 64x32 warp tiles, 3-stage swizzled
// cp.async ring, 2 CTAs/SM. Warps whose entire column range is padding skip compute.
__global__ void __launch_bounds__(256, 2)
hgemm3(const __nv_bfloat16* __restrict__ Ahp, const __nv_bfloat16* __restrict__ Alp,
       const __nv_bfloat16* __restrict__ Bhp, const __nv_bfloat16* __restrict__ Blp,
       float* __restrict__ C, int M, int Nreal, int K, int epi,
       const float* __restrict__ bbeta, const float* __restrict__ bg) {
    extern __shared__ __nv_bfloat16 smem[];   // 3 stages * 4 arrays * 128*32 bf16 = 96KB
    const int tid  = threadIdx.x;
    const int wid  = tid >> 5, lane = tid & 31;
    const int m0 = blockIdx.y * 128, n0 = blockIdx.x * 128;
    const int wm = (wid >> 2) * 64, wn = (wid & 3) * 32;
    const bool active = (n0 + wn) < Nreal;
    const uint32_t sbase = s2u(&smem[0]);

    const __nv_bfloat16* gsrc[4];
    gsrc[0] = Ahp + (size_t)m0 * K;
    gsrc[1] = Alp + (size_t)m0 * K;
    gsrc[2] = Bhp + (size_t)n0 * K;
    gsrc[3] = Blp + (size_t)n0 * K;

    float acc[4][4][4];
#pragma unroll
    for (int mi = 0; mi < 4; ++mi)
#pragma unroll
        for (int nj = 0; nj < 4; ++nj)
#pragma unroll
            for (int cc = 0; cc < 4; ++cc) acc[mi][nj][cc] = 0.f;

    auto load_stage = [&](int s, int kt) {
#pragma unroll
        for (int arr = 0; arr < 4; ++arr) {
            uint32_t abase = sbase + (uint32_t)s * 32768u + (uint32_t)arr * 8192u;
            const __nv_bfloat16* src = gsrc[arr];
#pragma unroll
            for (int i = 0; i < 2; ++i) {
                int lin = i * 256 + tid;
                int r = lin >> 2, c = lin & 3;
                uint32_t dst = abase + swz(r, c * 8);
                const void* sp = src + (size_t)r * K + kt + c * 8;
                asm volatile("cp.async.cg.shared.global [%0], [%1], 16;" :: "r"(dst), "l"(sp));
            }
        }
        asm volatile("cp.async.commit_group;");
    };

    const int KT = K / 32;
    load_stage(0, 0);
    if (KT > 1) load_stage(1, 32);

    for (int it = 0; it < KT; ++it) {
        if (it + 1 < KT) {
            asm volatile("cp.async.wait_group 1;");
        } else {
            asm volatile("cp.async.wait_group 0;");
        }
        __syncthreads();   // single barrier: stage it%3 visible AND iter it-1 reads done
        if (it + 2 < KT) load_stage((it + 2) % 3, (it + 2) * 32);

        if (active) {
            const uint32_t stg = sbase + (uint32_t)(it % 3) * 32768u;
            const uint32_t aHs = stg;
            const uint32_t aLs = stg + 8192u;
            const uint32_t bHs = stg + 16384u;
            const uint32_t bLs = stg + 24576u;

#pragma unroll
            for (int kk = 0; kk < 32; kk += 16) {
                uint32_t fbh[4][2], fbl[4][2];
#pragma unroll
                for (int j = 0; j < 2; ++j) {
                    int row = wn + j * 16 + (lane & 7) + ((lane >> 4) & 1) * 8;
                    int col = kk + ((lane >> 3) & 1) * 8;
                    uint32_t off = swz(row, col);
                    uint32_t t0, t1, t2, t3;
                    ldsm4(t0, t1, t2, t3, bHs + off);
                    fbh[j*2][0] = t0; fbh[j*2][1] = t1; fbh[j*2+1][0] = t2; fbh[j*2+1][1] = t3;
                    ldsm4(t0, t1, t2, t3, bLs + off);
                    fbl[j*2][0] = t0; fbl[j*2][1] = t1; fbl[j*2+1][0] = t2; fbl[j*2+1][1] = t3;
                }
#pragma unroll
                for (int mi = 0; mi < 4; ++mi) {
                    int row = wm + mi * 16 + (lane & 7) + ((lane >> 3) & 1) * 8;
                    int col = kk + ((lane >> 4) & 1) * 8;
                    uint32_t off = swz(row, col);
                    uint32_t ah0, ah1, ah2, ah3, al0, al1, al2, al3;
                    ldsm4(ah0, ah1, ah2, ah3, aHs + off);
                    ldsm4(al0, al1, al2, al3, aLs + off);
#pragma unroll
                    for (int nj = 0; nj < 4; ++nj)
                        mma_bf16(acc[mi][nj], ah0, ah1, ah2, ah3, fbh[nj][0], fbh[nj][1]);
#pragma unroll
                    for (int nj = 0; nj < 4; ++nj)
                        mma_bf16(acc[mi][nj], ah0, ah1, ah2, ah3, fbl[nj][0], fbl[nj][1]);
#pragma unroll
                    for (int nj = 0; nj < 4; ++nj)
                        mma_bf16(acc[mi][nj], al0, al1, al2, al3, fbh[nj][0], fbh[nj][1]);
                }
            }
        }
    }

    const int grp = lane >> 2, t2c = (lane & 3) << 1;
#pragma unroll
    for (int mi = 0; mi < 4; ++mi) {
#pragma unroll
        for (int nj = 0; nj < 4; ++nj) {
            int gm = m0 + wm + mi * 16 + grp;
            int gn = n0 + wn + nj * 8 + t2c;
            if (gn < Nreal) {
                float v0 = acc[mi][nj][0], v1 = acc[mi][nj][1];
                float v2 = acc[mi][nj][2], v3 = acc[mi][nj][3];
                if (epi && gn >= 1024) {
                    if (gn < 1032) {
                        v0 = 2.f / (1.f + expf(-(v0 + bbeta[gn - 1024])));
                        v1 = 2.f / (1.f + expf(-(v1 + bbeta[gn - 1023])));
                        v2 = 2.f / (1.f + expf(-(v2 + bbeta[gn - 1024])));
                        v3 = 2.f / (1.f + expf(-(v3 + bbeta[gn - 1023])));
                    } else {
                        v0 = 1.f / (1.f + expf(-(v0 + bg[gn - 1032])));
                        v1 = 1.f / (1.f + expf(-(v1 + bg[gn - 1031])));
                        v2 = 1.f / (1.f + expf(-(v2 + bg[gn - 1032])));
                        v3 = 1.f / (1.f + expf(-(v3 + bg[gn - 1031])));
                    }
                }
                float* p0 = C + (size_t)gm * Nreal + gn;
                float* p1 = C + (size_t)(gm + 8) * Nreal + gn;
                p0[0] = v0; p0[1] = v1;
                p1[0] = v2; p1[1] = v3;
            }
        }
    }
}

// -------------------- prep: normalize w, fold q*scale*eg, SoA streams ---------------
__global__ void __launch_bounds__(256) prep() {
    const float scale = 0.17677669529663687f;   // 32^-0.5
    int g    = blockIdx.x * 8 + (threadIdx.x >> 5);
    int lane = threadIdx.x & 31;
    int bh = g >> 12;
    int t  = g & 4095;
    int b = bh >> 3, h = bh & 7;
    const float* r = g_Y + (size_t)(b * Tq + t) * NC;

    float w = r[768 + h * 32 + lane];
    float ss = w * w;
    ss += __shfl_xor_sync(0xffffffffu, ss, 16);
    ss += __shfl_xor_sync(0xffffffffu, ss, 8);
    ss += __shfl_xor_sync(0xffffffffu, ss, 4);
    ss += __shfl_xor_sync(0xffffffffu, ss, 2);
    ss += __shfl_xor_sync(0xffffffffu, ss, 1);
    w = w / (sqrtf(ss) + 1e-6f);

    float v    = r[512 + h * 32 + lane];
    float k    = r[256 + h * 32 + lane];
    float q    = r[       h * 32 + lane];
    float beta = r[1024 + h];
    float eg   = r[1032 + h];   // sigmoid(zg) == exp(log_sigmoid(zg))

    size_t o = (size_t)g * 32 + lane;
    g_w[o] = w; g_v[o] = v; g_k[o] = k; g_q[o] = q * scale * eg;
    if (lane == 0) g_beta[g] = beta;
}

// -------------------- pass1: per-chunk transfer matrix P and injection A --------------------
// cp.async double-buffered SoA windows (R13 configuration).
__global__ void __launch_bounds__(WPB*32) scanPA() {
    __shared__ float wbuf[WPB][2][8][32];
    __shared__ float vbuf[WPB][2][8][32];
    __shared__ float kbuf[WPB][2][8][32];
    __shared__ float bbuf[WPB][2][8];

    const int wid  = threadIdx.x >> 5;
    const int lane = threadIdx.x & 31;
    const int wg   = blockIdx.x * WPB + wid;
    const int bh   = wg >> 6;
    const int c    = wg & 63;
    const size_t sbase = ((size_t)bh * Tq + (size_t)c * LCH) * 32;
    const size_t bbase = (size_t)bh * Tq + (size_t)c * LCH;

    auto issue = [&](int wnd, int bf) {
        size_t goff = sbase + (size_t)wnd * 256;
        uint32_t dw = s2u(&wbuf[wid][bf][0][0]);
        uint32_t dv = s2u(&vbuf[wid][bf][0][0]);
        uint32_t dk = s2u(&kbuf[wid][bf][0][0]);
#pragma unroll
        for (int i = 0; i < 2; ++i) {
            int e4 = i * 32 + lane;
            const void* sw = (const float4*)(g_w + goff) + e4;
            const void* sv = (const float4*)(g_v + goff) + e4;
            const void* sk = (const float4*)(g_k + goff) + e4;
            asm volatile("cp.async.cg.shared.global [%0], [%1], 16;" :: "r"(dw + e4*16u), "l"(sw));
            asm volatile("cp.async.cg.shared.global [%0], [%1], 16;" :: "r"(dv + e4*16u), "l"(sv));
            asm volatile("cp.async.cg.shared.global [%0], [%1], 16;" :: "r"(dk + e4*16u), "l"(sk));
        }
        if (lane < 8) {
            uint32_t db = s2u(&bbuf[wid][bf][lane]);
            asm volatile("cp.async.ca.shared.global [%0], [%1], 4;"
                         :: "r"(db), "l"(g_beta + bbase + wnd * 8 + lane));
        }
        asm volatile("cp.async.commit_group;");
    };

    issue(0, 0);
    issue(1, 1);
    asm volatile("cp.async.wait_group 1;" ::: "memory");
    __syncwarp();

    float P[32], A[32];
#pragma unroll
    for (int m = 0; m < 32; ++m) { P[m] = (m == lane) ? 1.f : 0.f; A[m] = 0.f; }

    for (int w = 0; w < 8; ++w) {
        const int cur = w & 1;
#pragma unroll
        for (int t = 0; t < 8; ++t) {
            const float4* w4p = (const float4*)&wbuf[wid][cur][t][0];
            const float4* v4p = (const float4*)&vbuf[wid][cur][t][0];
            float k    = kbuf[wid][cur][t][lane];
            float beta = bbuf[wid][cur][t];
            float p0 = 0.f, p1 = 0.f, p2 = 0.f, p3 = 0.f;
            float a0 = 0.f, a1 = 0.f, a2 = 0.f, a3 = 0.f;
            float4 w4[8];
#pragma unroll
            for (int j = 0; j < 8; ++j) {
                w4[j] = w4p[j];
                p0 = fmaf(P[4*j+0], w4[j].x, p0);
                p1 = fmaf(P[4*j+1], w4[j].y, p1);
                p2 = fmaf(P[4*j+2], w4[j].z, p2);
                p3 = fmaf(P[4*j+3], w4[j].w, p3);
                a0 = fmaf(A[4*j+0], w4[j].x, a0);
                a1 = fmaf(A[4*j+1], w4[j].y, a1);
                a2 = fmaf(A[4*j+2], w4[j].z, a2);
                a3 = fmaf(A[4*j+3], w4[j].w, a3);
            }
            float cp = -beta * ((p0 + p1) + (p2 + p3));
            float ca = -beta * ((a0 + a1) + (a2 + a3));
#pragma unroll
            for (int j = 0; j < 8; ++j) {
                float4 v4 = v4p[j];
                P[4*j+0] = fmaf(cp, w4[j].x, P[4*j+0]);
                P[4*j+1] = fmaf(cp, w4[j].y, P[4*j+1]);
                P[4*j+2] = fmaf(cp, w4[j].z, P[4*j+2]);
                P[4*j+3] = fmaf(cp, w4[j].w, P[4*j+3]);
                A[4*j+0] = fmaf(ca, w4[j].x, fmaf(k, v4.x, A[4*j+0]));
                A[4*j+1] = fmaf(ca, w4[j].y, fmaf(k, v4.y, A[4*j+1]));
                A[4*j+2] = fmaf(ca, w4[j].z, fmaf(k, v4.z, A[4*j+2]));
                A[4*j+3] = fmaf(ca, w4[j].w, fmaf(k, v4.w, A[4*j+3]));
            }
        }
        if (w < 6) {
            __syncwarp();
            issue(w + 2, cur);
            asm volatile("cp.async.wait_group 1;" ::: "memory");
            __syncwarp();
        } else if (w == 6) {
            asm volatile("cp.async.wait_group 0;" ::: "memory");
            __syncwarp();
        }
    }

    size_t obase = ((size_t)bh * CCH + c) * 1024 + (size_t)lane * 32;
#pragma unroll
    for (int j = 0; j < 8; ++j) {
        *(float4*)&g_P[obase + 4*j] = make_float4(P[4*j], P[4*j+1], P[4*j+2], P[4*j+3]);
        *(float4*)&g_A[obase + 4*j] = make_float4(A[4*j], A[4*j+1], A[4*j+2], A[4*j+3]);
    }
}

// -------------------- combine: sequential chunk-boundary states --------------------
__global__ void __launch_bounds__(1024, 1) combine() {
    __shared__ float Ssh[32][32];
    const int bh = blockIdx.x;
    const int tid = threadIdx.x;
    const int d = tid >> 5, m = tid & 31;

    float s = 0.f;
    for (int c = 0; c < CCH; ++c) {
        size_t base = ((size_t)bh * CCH + c) * 1024;
        g_S0[base + tid] = s;
        Ssh[d][m] = s;
        __syncthreads();
        float acc = g_A[base + tid];
        const float* Pc = g_P + base;
#pragma unroll
        for (int mm = 0; mm < 32; ++mm)
            acc = fmaf(Ssh[d][mm], Pc[mm * 32 + m], acc);
        __syncthreads();
        s = acc;
    }
}

// -------------------- pass2: replay chunks, emit outputs as bf16 hi/lo ----------------
// cp.async double-buffered; dynamic smem (51456 B). R13 configuration.
__global__ void __launch_bounds__(WPB*32) scanOut() {
    extern __shared__ float dyn[];
    float (*wbuf)[2][8][32] = (float(*)[2][8][32])(dyn);
    float (*vbuf)[2][8][32] = (float(*)[2][8][32])(dyn + 2048);
    float (*kbuf)[2][8][32] = (float(*)[2][8][32])(dyn + 4096);
    float (*qbuf)[2][8][32] = (float(*)[2][8][32])(dyn + 6144);
    float (*part)[32][36]   = (float(*)[32][36])(dyn + 8192);
    float (*bbuf)[2][8]     = (float(*)[2][8])(dyn + 8192 + WPB*32*36);

    const int wid  = threadIdx.x >> 5;
    const int lane = threadIdx.x & 31;
    const int wg   = blockIdx.x * WPB + wid;
    const int bh   = wg >> 6;
    const int c    = wg & 63;
    const int b = bh >> 3, h = bh & 7;
    const size_t sbase = ((size_t)bh * Tq + (size_t)c * LCH) * 32;
    const size_t bbase = (size_t)bh * Tq + (size_t)c * LCH;
    const size_t s0base = ((size_t)bh * CCH + c) * 1024 + (size_t)lane * 32;
    const int rowbase = b * Tq + c * LCH;

    auto issue = [&](int wnd, int bf) {
        size_t goff = sbase + (size_t)wnd * 256;
        uint32_t dw = s2u(&wbuf[wid][bf][0][0]);
        uint32_t dv = s2u(&vbuf[wid][bf][0][0]);
        uint32_t dk = s2u(&kbuf[wid][bf][0][0]);
        uint32_t dq = s2u(&qbuf[wid][bf][0][0]);
#pragma unroll
        for (int i = 0; i < 2; ++i) {
            int e4 = i * 32 + lane;
            asm volatile("cp.async.cg.shared.global [%0], [%1], 16;"
                         :: "r"(dw + e4*16u), "l"((const float4*)(g_w + goff) + e4));
            asm volatile("cp.async.cg.shared.global [%0], [%1], 16;"
                         :: "r"(dv + e4*16u), "l"((const float4*)(g_v + goff) + e4));
            asm volatile("cp.async.cg.shared.global [%0], [%1], 16;"
                         :: "r"(dk + e4*16u), "l"((const float4*)(g_k + goff) + e4));
            asm volatile("cp.async.cg.shared.global [%0], [%1], 16;"
                         :: "r"(dq + e4*16u), "l"((const float4*)(g_q + goff) + e4));
        }
        if (lane < 8) {
            uint32_t db = s2u(&bbuf[wid][bf][lane]);
            asm volatile("cp.async.ca.shared.global [%0], [%1], 4;"
                         :: "r"(db), "l"(g_beta + bbase + wnd * 8 + lane));
        }
        asm volatile("cp.async.commit_group;");
    };

    issue(0, 0);
    issue(1, 1);
    asm volatile("cp.async.wait_group 1;" ::: "memory");
    __syncwarp();

    float S[32];
#pragma unroll
    for (int j = 0; j < 8; ++j) {
        float4 s0 = *(const float4*)&g_S0[s0base + 4*j];
        S[4*j] = s0.x; S[4*j+1] = s0.y; S[4*j+2] = s0.z; S[4*j+3] = s0.w;
    }

    for (int w = 0; w < 8; ++w) {
        const int cur = w & 1;
#pragma unroll
        for (int t = 0; t < 8; ++t) {
            const float4* w4p = (const float4*)&wbuf[wid][cur][t][0];
            const float4* v4p = (const float4*)&vbuf[wid][cur][t][0];
            float k    = kbuf[wid][cur][t][lane];
            float q    = qbuf[wid][cur][t][lane];
            float beta = bbuf[wid][cur][t];
            float a0 = 0.f, a1 = 0.f, a2 = 0.f, a3 = 0.f;
            float4 w4[8];
#pragma unroll
            for (int j = 0; j < 8; ++j) {
                w4[j] = w4p[j];
                a0 = fmaf(S[4*j+0], w4[j].x, a0);
                a1 = fmaf(S[4*j+1], w4[j].y, a1);
                a2 = fmaf(S[4*j+2], w4[j].z, a2);
                a3 = fmaf(S[4*j+3], w4[j].w, a3);
            }
            float cs = -beta * ((a0 + a1) + (a2 + a3));
#pragma unroll
            for (int j = 0; j < 8; ++j) {
                float4 v4 = v4p[j];
                S[4*j+0] = fmaf(cs, w4[j].x, fmaf(k, v4.x, S[4*j+0]));
                S[4*j+1] = fmaf(cs, w4[j].y, fmaf(k, v4.y, S[4*j+1]));
                S[4*j+2] = fmaf(cs, w4[j].z, fmaf(k, v4.z, S[4*j+2]));
                S[4*j+3] = fmaf(cs, w4[j].w, fmaf(k, v4.w, S[4*j+3]));
            }
#pragma unroll
            for (int j = 0; j < 8; ++j) {
                *(float4*)&part[wid][lane][4*j] =
                    make_float4(q * S[4*j], q * S[4*j+1], q * S[4*j+2], q * S[4*j+3]);
            }
            __syncwarp();
            float o0 = 0.f, o1 = 0.f, o2 = 0.f, o3 = 0.f;
#pragma unroll
            for (int dd = 0; dd < 32; dd += 4) {
                o0 += part[wid][dd+0][lane];
                o1 += part[wid][dd+1][lane];
                o2 += part[wid][dd+2][lane];
                o3 += part[wid][dd+3][lane];
            }
            float o = (o0 + o1) + (o2 + o3);
            size_t oidx = (size_t)(rowbase + w * 8 + t) * 256 + h * 32 + lane;
            __nv_bfloat16 hi, lo;
            bf16split(o, hi, lo);
            g_atth[oidx] = hi; g_attl[oidx] = lo;
            __syncwarp();
        }
        if (w < 6) {
            __syncwarp();
            issue(w + 2, cur);
            asm volatile("cp.async.wait_group 1;" ::: "memory");
            __syncwarp();
        } else if (w == 6) {
            asm volatile("cp.async.wait_group 0;" ::: "memory");
            __syncwarp();
        }
    }
}

// -------------------- launch --------------------
extern "C" void kernel_launch(void* const* d_in, const int* in_sizes, int n_in,
                              void* d_out, int out_size) {
    const float* x     = (const float*)d_in[0];
    const float* Wq    = (const float*)d_in[1];
    const float* Wk    = (const float*)d_in[2];
    const float* Wv    = (const float*)d_in[3];
    const float* Ww    = (const float*)d_in[4];
    const float* Wbeta = (const float*)d_in[5];
    const float* bbeta = (const float*)d_in[6];
    const float* Wg    = (const float*)d_in[7];
    const float* bg    = (const float*)d_in[8];
    const float* Wo    = (const float*)d_in[9];
    float* out = (float*)d_out;

    void *pY, *pXh, *pXl, *pWh, *pWl, *pAh, *pAl, *pWoh, *pWol;
    cudaGetSymbolAddress(&pY,   g_Y);
    cudaGetSymbolAddress(&pXh,  g_xh);
    cudaGetSymbolAddress(&pXl,  g_xl);
    cudaGetSymbolAddress(&pWh,  g_Wh);
    cudaGetSymbolAddress(&pWl,  g_Wl);
    cudaGetSymbolAddress(&pAh,  g_atth);
    cudaGetSymbolAddress(&pAl,  g_attl);
    cudaGetSymbolAddress(&pWoh, g_woh);
    cudaGetSymbolAddress(&pWol, g_wol);

    const int SMEM = 3 * 4 * 128 * 32 * 2;   // 98304 bytes (3 swizzled 32KB stages)
    cudaFuncSetAttribute(hgemm3, cudaFuncAttributeMaxDynamicSharedMemorySize, SMEM);
    const int SCAN_SMEM = (8192 + WPB*32*36 + WPB*2*8) * 4;   // 51456 bytes
    cudaFuncSetAttribute(scanOut, cudaFuncAttributeMaxDynamicSharedMemorySize, SCAN_SMEM);

    // 1) fused conversions: pack/split W, split x, split Wo
    cvtAll<<<10784, 256>>>(x, Wq, Wk, Wv, Ww, Wbeta, Wg, Wo);

    // 2) fused projection GEMM + activations: Y[16384,1040] = x @ W^T (tensor cores)
    hgemm3<<<dim3(NCP / 128, MROWS / 128), 256, SMEM>>>(
        (const __nv_bfloat16*)pXh, (const __nv_bfloat16*)pXl,
        (const __nv_bfloat16*)pWh, (const __nv_bfloat16*)pWl,
        (float*)pY, MROWS, NC, HIDq, 1, bbeta, bg);

    // 3) normalize w, fold scales, pack SoA recurrence streams
    prep<<<16384, 256>>>();

    // 4) chunked associative scan over the recurrence
    scanPA<<<(BH * CCH) / WPB, WPB * 32>>>();
    combine<<<BH, 1024>>>();
    scanOut<<<(BH * CCH) / WPB, WPB * 32, SCAN_SMEM>>>();

    // 5) output projection: out[16384,512] = att @ Wo^T (tensor cores)
    hgemm3<<<dim3(HIDq / 128, MROWS / 128), 256, SMEM>>>(
        (const __nv_bfloat16*)pAh, (const __nv_bfloat16*)pAl,
        (const __nv_bfloat16*)pWoh, (const __nv_bfloat16*)pWol,
        out, MROWS, HIDq, Hh * Dd, 0, nullptr, nullptr);
}

// round 16
// speedup vs baseline: 1.0577x; 1.0423x over previous
#include <cuda_runtime.h>
#include <cuda_bf16.h>
#include <cstdint>
#include <math.h>

// Problem constants
#define Bq   4
#define Tq   4096
#define Hh   8
#define Dd   32
#define HIDq 512
#define NC   1040            // packed projection columns: q256 k256 v256 w256 beta8 g8
#define NCP  1152            // NC padded to multiple of 128
#define MROWS (Bq*Tq)        // 16384
#define BH   (Bq*Hh)         // 32
#define CCH  64              // chunks
#define LCH  64              // steps per chunk
#define WPB  4               // warps per block in scan kernels

// -------------------- scratch (device globals; zero-initialized, no allocation) ----
__device__ __nv_bfloat16  g_Wh[(size_t)NCP * HIDq];       // packed weights hi (pad rows zero)
__device__ __nv_bfloat16  g_Wl[(size_t)NCP * HIDq];       // packed weights lo
__device__ __nv_bfloat16  g_xh[(size_t)MROWS * HIDq];     // x hi (16 MB)
__device__ __nv_bfloat16  g_xl[(size_t)MROWS * HIDq];     // x lo
__device__ __nv_bfloat16  g_woh[(size_t)HIDq * 256];      // Wo hi
__device__ __nv_bfloat16  g_wol[(size_t)HIDq * 256];      // Wo lo
__device__ __nv_bfloat16  g_atth[(size_t)MROWS * 256];    // attention out hi (8 MB)
__device__ __nv_bfloat16  g_attl[(size_t)MROWS * 256];    // attention out lo
__device__ float  g_w[(size_t)BH * Tq * Dd];              // w (SoA streams; normalized by prep)
__device__ float  g_v[(size_t)BH * Tq * Dd];
__device__ float  g_k[(size_t)BH * Tq * Dd];
__device__ float  g_q[(size_t)BH * Tq * Dd];              // q (prep folds scale*eg)
__device__ float  g_eg[(size_t)BH * Tq];                  // sigmoid(zg+bg)
__device__ float  g_beta[(size_t)BH * Tq];                // beta (final)
__device__ float  g_P [(size_t)BH * CCH * 1024];          // chunk transfer matrices
__device__ float  g_A [(size_t)BH * CCH * 1024];          // chunk injections
__device__ float  g_S0[(size_t)BH * CCH * 1024];          // state at chunk starts

// -------------------- helpers --------------------
__device__ __forceinline__ void bf16split(float v, __nv_bfloat16& hi, __nv_bfloat16& lo) {
    hi = __float2bfloat16(v);
    lo = __float2bfloat16(v - __bfloat162float(hi));
}

__device__ __forceinline__ void ldsm4(uint32_t& r0, uint32_t& r1, uint32_t& r2, uint32_t& r3,
                                      uint32_t addr) {
    asm volatile("ldmatrix.sync.aligned.m8n8.x4.shared.b16 {%0,%1,%2,%3}, [%4];"
        : "=r"(r0), "=r"(r1), "=r"(r2), "=r"(r3) : "r"(addr));
}

__device__ __forceinline__ void mma_bf16(float* d, uint32_t a0, uint32_t a1, uint32_t a2,
                                         uint32_t a3, uint32_t b0, uint32_t b1) {
    asm volatile("mma.sync.aligned.m16n8k16.row.col.f32.bf16.bf16.f32 "
        "{%0,%1,%2,%3}, {%4,%5,%6,%7}, {%8,%9}, {%0,%1,%2,%3};"
        : "+f"(d[0]), "+f"(d[1]), "+f"(d[2]), "+f"(d[3])
        : "r"(a0), "r"(a1), "r"(a2), "r"(a3), "r"(b0), "r"(b1));
}

// swizzled smem byte offset within one 128x32 bf16 array: row stride 64B, 4 chunks of 16B
__device__ __forceinline__ uint32_t swz(int row, int col) {
    uint32_t chunk = (uint32_t)(col >> 3);
    return (uint32_t)(row * 64) + ((chunk ^ (((uint32_t)row >> 1) & 3u)) << 4);
}

__device__ __forceinline__ uint32_t s2u(const void* p) {
    return (uint32_t)__cvta_generic_to_shared(p);
}

// -------------------- fused conversions: pack/split W, split x, split Wo ------------
// blockIdx ranges: [0,2080) packW, [2080,10272) cvtA, [10272,10784) cvtWo
__global__ void __launch_bounds__(256) cvtAll(
        const float* __restrict__ x,
        const float* __restrict__ wq, const float* __restrict__ wk,
        const float* __restrict__ wv, const float* __restrict__ ww,
        const float* __restrict__ wb, const float* __restrict__ wg,
        const float* __restrict__ Wo) {
    int b = blockIdx.x;
    if (b < 2080) {
        int i = b * 256 + threadIdx.x;           // 0 .. 532479
        int r = i >> 9, c = i & 511;
        float v;
        if      (r < 256)  v = wq[i];
        else if (r < 512)  v = wk[(r - 256)  * HIDq + c];
        else if (r < 768)  v = wv[(r - 512)  * HIDq + c];
        else if (r < 1024) v = ww[(r - 768)  * HIDq + c];
        else if (r < 1032) v = wb[(r - 1024) * HIDq + c];
        else               v = wg[(r - 1032) * HIDq + c];
        __nv_bfloat16 hi, lo;
        bf16split(v, hi, lo);
        g_Wh[i] = hi; g_Wl[i] = lo;
    } else if (b < 10272) {
        int i = (b - 2080) * 256 + threadIdx.x;  // float4 index, 2097152 total
        float4 v = ((const float4*)x)[i];
        __nv_bfloat16 h0, l0, h1, l1, h2, l2, h3, l3;
        bf16split(v.x, h0, l0); bf16split(v.y, h1, l1);
        bf16split(v.z, h2, l2); bf16split(v.w, h3, l3);
        ((__nv_bfloat162*)g_xh)[2*i]   = __halves2bfloat162(h0, h1);
        ((__nv_bfloat162*)g_xh)[2*i+1] = __halves2bfloat162(h2, h3);
        ((__nv_bfloat162*)g_xl)[2*i]   = __halves2bfloat162(l0, l1);
        ((__nv_bfloat162*)g_xl)[2*i+1] = __halves2bfloat162(l2, l3);
    } else {
        int i = (b - 10272) * 256 + threadIdx.x; // 0 .. 131071
        __nv_bfloat16 hi, lo;
        bf16split(Wo[i], hi, lo);
        g_woh[i] = hi; g_wol[i] = lo;
    }
}

// -------------------- tensor-core GEMM: 3-term bf16 split, 128x128x32, 8 warps ------
// mode 0: plain row-major store to C (ldC = Nreal).
// mode 1: scatter q/k/v/w into SoA streams; beta/g sigmoids into g_beta/g_eg.
__global__ void __launch_bounds__(256, 2)
hgemm3(const __nv_bfloat16* __restrict__ Ahp, const __nv_bfloat16* __restrict__ Alp,
       const __nv_bfloat16* __restrict__ Bhp, const __nv_bfloat16* __restrict__ Blp,
       float* __restrict__ C, int Nreal, int K, int mode,
       const float* __restrict__ bbeta, const float* __restrict__ bg) {
    extern __shared__ __nv_bfloat16 smem[];   // 3 stages * 4 arrays * 128*32 bf16 = 96KB
    const int tid  = threadIdx.x;
    const int wid  = tid >> 5, lane = tid & 31;
    const int m0 = blockIdx.y * 128, n0 = blockIdx.x * 128;
    const int wm = (wid >> 2) * 64, wn = (wid & 3) * 32;
    const bool active = (n0 + wn) < Nreal;
    const uint32_t sbase = s2u(&smem[0]);

    const __nv_bfloat16* gsrc[4];
    gsrc[0] = Ahp + (size_t)m0 * K;
    gsrc[1] = Alp + (size_t)m0 * K;
    gsrc[2] = Bhp + (size_t)n0 * K;
    gsrc[3] = Blp + (size_t)n0 * K;

    float acc[4][4][4];
#pragma unroll
    for (int mi = 0; mi < 4; ++mi)
#pragma unroll
        for (int nj = 0; nj < 4; ++nj)
#pragma unroll
            for (int cc = 0; cc < 4; ++cc) acc[mi][nj][cc] = 0.f;

    auto load_stage = [&](int s, int kt) {
#pragma unroll
        for (int arr = 0; arr < 4; ++arr) {
            uint32_t abase = sbase + (uint32_t)s * 32768u + (uint32_t)arr * 8192u;
            const __nv_bfloat16* src = gsrc[arr];
#pragma unroll
            for (int i = 0; i < 2; ++i) {
                int lin = i * 256 + tid;
                int r = lin >> 2, c = lin & 3;
                uint32_t dst = abase + swz(r, c * 8);
                const void* sp = src + (size_t)r * K + kt + c * 8;
                asm volatile("cp.async.cg.shared.global [%0], [%1], 16;" :: "r"(dst), "l"(sp));
            }
        }
        asm volatile("cp.async.commit_group;");
    };

    const int KT = K / 32;
    load_stage(0, 0);
    if (KT > 1) load_stage(1, 32);

    for (int it = 0; it < KT; ++it) {
        if (it + 1 < KT) {
            asm volatile("cp.async.wait_group 1;");
        } else {
            asm volatile("cp.async.wait_group 0;");
        }
        __syncthreads();   // single barrier: stage it%3 visible AND iter it-1 reads done
        if (it + 2 < KT) load_stage((it + 2) % 3, (it + 2) * 32);

        if (active) {
            const uint32_t stg = sbase + (uint32_t)(it % 3) * 32768u;
            const uint32_t aHs = stg;
            const uint32_t aLs = stg + 8192u;
            const uint32_t bHs = stg + 16384u;
            const uint32_t bLs = stg + 24576u;

#pragma unroll
            for (int kk = 0; kk < 32; kk += 16) {
                uint32_t fbh[4][2], fbl[4][2];
#pragma unroll
                for (int j = 0; j < 2; ++j) {
                    int row = wn + j * 16 + (lane & 7) + ((lane >> 4) & 1) * 8;
                    int col = kk + ((lane >> 3) & 1) * 8;
                    uint32_t off = swz(row, col);
                    uint32_t t0, t1, t2, t3;
                    ldsm4(t0, t1, t2, t3, bHs + off);
                    fbh[j*2][0] = t0; fbh[j*2][1] = t1; fbh[j*2+1][0] = t2; fbh[j*2+1][1] = t3;
                    ldsm4(t0, t1, t2, t3, bLs + off);
                    fbl[j*2][0] = t0; fbl[j*2][1] = t1; fbl[j*2+1][0] = t2; fbl[j*2+1][1] = t3;
                }
#pragma unroll
                for (int mi = 0; mi < 4; ++mi) {
                    int row = wm + mi * 16 + (lane & 7) + ((lane >> 3) & 1) * 8;
                    int col = kk + ((lane >> 4) & 1) * 8;
                    uint32_t off = swz(row, col);
                    uint32_t ah0, ah1, ah2, ah3, al0, al1, al2, al3;
                    ldsm4(ah0, ah1, ah2, ah3, aHs + off);
                    ldsm4(al0, al1, al2, al3, aLs + off);
#pragma unroll
                    for (int nj = 0; nj < 4; ++nj)
                        mma_bf16(acc[mi][nj], ah0, ah1, ah2, ah3, fbh[nj][0], fbh[nj][1]);
#pragma unroll
                    for (int nj = 0; nj < 4; ++nj)
                        mma_bf16(acc[mi][nj], ah0, ah1, ah2, ah3, fbl[nj][0], fbl[nj][1]);
#pragma unroll
                    for (int nj = 0; nj < 4; ++nj)
                        mma_bf16(acc[mi][nj], al0, al1, al2, al3, fbh[nj][0], fbh[nj][1]);
                }
            }
        }
    }

    const int grp = lane >> 2, t2c = (lane & 3) << 1;
    if (mode == 0) {
#pragma unroll
        for (int mi = 0; mi < 4; ++mi) {
#pragma unroll
            for (int nj = 0; nj < 4; ++nj) {
                int gm = m0 + wm + mi * 16 + grp;
                int gn = n0 + wn + nj * 8 + t2c;
                float* p0 = C + (size_t)gm * Nreal + gn;
                float* p1 = C + (size_t)(gm + 8) * Nreal + gn;
                p0[0] = acc[mi][nj][0]; p0[1] = acc[mi][nj][1];
                p1[0] = acc[mi][nj][2]; p1[1] = acc[mi][nj][3];
            }
        }
    } else {
#pragma unroll
        for (int mi = 0; mi < 4; ++mi) {
#pragma unroll
            for (int nj = 0; nj < 4; ++nj) {
                int gm = m0 + wm + mi * 16 + grp;
                int gn = n0 + wn + nj * 8 + t2c;
                int b = gm >> 12, t = gm & 4095;
                float v0 = acc[mi][nj][0], v1 = acc[mi][nj][1];
                float v2 = acc[mi][nj][2], v3 = acc[mi][nj][3];
                if (gn < 1024) {
                    int arr = gn >> 8, h = (gn >> 5) & 7, d = gn & 31;
                    float* dst = (arr == 0) ? g_q : (arr == 1) ? g_k
                               : (arr == 2) ? g_v : g_w;
                    size_t i0 = (((size_t)(b * 8 + h) * Tq + t) << 5) + d;
                    *(float2*)&dst[i0]       = make_float2(v0, v1);
                    *(float2*)&dst[i0 + 256] = make_float2(v2, v3);   // t+8
                } else if (gn < 1032) {
                    int h = gn - 1024;
                    size_t i0 = (size_t)(b * 8 + h)     * Tq + t;
                    size_t i1 = (size_t)(b * 8 + h + 1) * Tq + t;
                    g_beta[i0]     = 2.f / (1.f + expf(-(v0 + bbeta[h])));
                    g_beta[i1]     = 2.f / (1.f + expf(-(v1 + bbeta[h + 1])));
                    g_beta[i0 + 8] = 2.f / (1.f + expf(-(v2 + bbeta[h])));
                    g_beta[i1 + 8] = 2.f / (1.f + expf(-(v3 + bbeta[h + 1])));
                } else if (gn < 1040) {
                    int h = gn - 1032;
                    size_t i0 = (size_t)(b * 8 + h)     * Tq + t;
                    size_t i1 = (size_t)(b * 8 + h + 1) * Tq + t;
                    g_eg[i0]     = 1.f / (1.f + expf(-(v0 + bg[h])));
                    g_eg[i1]     = 1.f / (1.f + expf(-(v1 + bg[h + 1])));
                    g_eg[i0 + 8] = 1.f / (1.f + expf(-(v2 + bg[h])));
                    g_eg[i1 + 8] = 1.f / (1.f + expf(-(v3 + bg[h + 1])));
                }
                // gn >= 1040: padding, discard
            }
        }
    }
}

// -------------------- prep: normalize w in-stream, fold q*scale*eg in-stream --------
__global__ void __launch_bounds__(256) prep() {
    const float scale = 0.17677669529663687f;   // 32^-0.5
    int g    = blockIdx.x * 8 + (threadIdx.x >> 5);   // bh*Tq + t
    int lane = threadIdx.x & 31;
    size_t o = (size_t)g * 32 + lane;

    float w = g_w[o];
    float ss = w * w;
    ss += __shfl_xor_sync(0xffffffffu, ss, 16);
    ss += __shfl_xor_sync(0xffffffffu, ss, 8);
    ss += __shfl_xor_sync(0xffffffffu, ss, 4);
    ss += __shfl_xor_sync(0xffffffffu, ss, 2);
    ss += __shfl_xor_sync(0xffffffffu, ss, 1);
    g_w[o] = w / (sqrtf(ss) + 1e-6f);

    float eg = g_eg[g];
    g_q[o] = g_q[o] * (scale * eg);
}

// -------------------- pass1: per-chunk transfer matrix P and injection A --------------------
// cp.async double-buffered SoA windows.
__global__ void __launch_bounds__(WPB*32) scanPA() {
    __shared__ float wbuf[WPB][2][8][32];
    __shared__ float vbuf[WPB][2][8][32];
    __shared__ float kbuf[WPB][2][8][32];
    __shared__ float bbuf[WPB][2][8];

    const int wid  = threadIdx.x >> 5;
    const int lane = threadIdx.x & 31;
    const int wg   = blockIdx.x * WPB + wid;
    const int bh   = wg >> 6;
    const int c    = wg & 63;
    const size_t sbase = ((size_t)bh * Tq + (size_t)c * LCH) * 32;
    const size_t bbase = (size_t)bh * Tq + (size_t)c * LCH;

    auto issue = [&](int wnd, int bf) {
        size_t goff = sbase + (size_t)wnd * 256;
        uint32_t dw = s2u(&wbuf[wid][bf][0][0]);
        uint32_t dv = s2u(&vbuf[wid][bf][0][0]);
        uint32_t dk = s2u(&kbuf[wid][bf][0][0]);
#pragma unroll
        for (int i = 0; i < 2; ++i) {
            int e4 = i * 32 + lane;
            const void* sw = (const float4*)(g_w + goff) + e4;
            const void* sv = (const float4*)(g_v + goff) + e4;
            const void* sk = (const float4*)(g_k + goff) + e4;
            asm volatile("cp.async.cg.shared.global [%0], [%1], 16;" :: "r"(dw + e4*16u), "l"(sw));
            asm volatile("cp.async.cg.shared.global [%0], [%1], 16;" :: "r"(dv + e4*16u), "l"(sv));
            asm volatile("cp.async.cg.shared.global [%0], [%1], 16;" :: "r"(dk + e4*16u), "l"(sk));
        }
        if (lane < 8) {
            uint32_t db = s2u(&bbuf[wid][bf][lane]);
            asm volatile("cp.async.ca.shared.global [%0], [%1], 4;"
                         :: "r"(db), "l"(g_beta + bbase + wnd * 8 + lane));
        }
        asm volatile("cp.async.commit_group;");
    };

    issue(0, 0);
    issue(1, 1);
    asm volatile("cp.async.wait_group 1;" ::: "memory");
    __syncwarp();

    float P[32], A[32];
#pragma unroll
    for (int m = 0; m < 32; ++m) { P[m] = (m == lane) ? 1.f : 0.f; A[m] = 0.f; }

    for (int w = 0; w < 8; ++w) {
        const int cur = w & 1;
#pragma unroll
        for (int t = 0; t < 8; ++t) {
            const float4* w4p = (const float4*)&wbuf[wid][cur][t][0];
            const float4* v4p = (const float4*)&vbuf[wid][cur][t][0];
            float k    = kbuf[wid][cur][t][lane];
            float beta = bbuf[wid][cur][t];
            float p0 = 0.f, p1 = 0.f, p2 = 0.f, p3 = 0.f;
            float a0 = 0.f, a1 = 0.f, a2 = 0.f, a3 = 0.f;
            float4 w4[8];
#pragma unroll
            for (int j = 0; j < 8; ++j) {
                w4[j] = w4p[j];
                p0 = fmaf(P[4*j+0], w4[j].x, p0);
                p1 = fmaf(P[4*j+1], w4[j].y, p1);
                p2 = fmaf(P[4*j+2], w4[j].z, p2);
                p3 = fmaf(P[4*j+3], w4[j].w, p3);
                a0 = fmaf(A[4*j+0], w4[j].x, a0);
                a1 = fmaf(A[4*j+1], w4[j].y, a1);
                a2 = fmaf(A[4*j+2], w4[j].z, a2);
                a3 = fmaf(A[4*j+3], w4[j].w, a3);
            }
            float cp = -beta * ((p0 + p1) + (p2 + p3));
            float ca = -beta * ((a0 + a1) + (a2 + a3));
#pragma unroll
            for (int j = 0; j < 8; ++j) {
                float4 v4 = v4p[j];
                P[4*j+0] = fmaf(cp, w4[j].x, P[4*j+0]);
                P[4*j+1] = fmaf(cp, w4[j].y, P[4*j+1]);
                P[4*j+2] = fmaf(cp, w4[j].z, P[4*j+2]);
                P[4*j+3] = fmaf(cp, w4[j].w, P[4*j+3]);
                A[4*j+0] = fmaf(ca, w4[j].x, fmaf(k, v4.x, A[4*j+0]));
                A[4*j+1] = fmaf(ca, w4[j].y, fmaf(k, v4.y, A[4*j+1]));
                A[4*j+2] = fmaf(ca, w4[j].z, fmaf(k, v4.z, A[4*j+2]));
                A[4*j+3] = fmaf(ca, w4[j].w, fmaf(k, v4.w, A[4*j+3]));
            }
        }
        if (w < 6) {
            __syncwarp();
            issue(w + 2, cur);
            asm volatile("cp.async.wait_group 1;" ::: "memory");
            __syncwarp();
        } else if (w == 6) {
            asm volatile("cp.async.wait_group 0;" ::: "memory");
            __syncwarp();
        }
    }

    size_t obase = ((size_t)bh * CCH + c) * 1024 + (size_t)lane * 32;
#pragma unroll
    for (int j = 0; j < 8; ++j) {
        *(float4*)&g_P[obase + 4*j] = make_float4(P[4*j], P[4*j+1], P[4*j+2], P[4*j+3]);
        *(float4*)&g_A[obase + 4*j] = make_float4(A[4*j], A[4*j+1], A[4*j+2], A[4*j+3]);
    }
}

// -------------------- combine: sequential chunk-boundary states --------------------
__global__ void __launch_bounds__(1024, 1) combine() {
    __shared__ float Ssh[32][32];
    const int bh = blockIdx.x;
    const int tid = threadIdx.x;
    const int d = tid >> 5, m = tid & 31;

    float s = 0.f;
    for (int c = 0; c < CCH; ++c) {
        size_t base = ((size_t)bh * CCH + c) * 1024;
        g_S0[base + tid] = s;
        Ssh[d][m] = s;
        __syncthreads();
        float acc = g_A[base + tid];
        const float* Pc = g_P + base;
#pragma unroll
        for (int mm = 0; mm < 32; ++mm)
            acc = fmaf(Ssh[d][mm], Pc[mm * 32 + m], acc);
        __syncthreads();
        s = acc;
    }
}

// -------------------- pass2: replay chunks, emit outputs as bf16 hi/lo ----------------
// cp.async double-buffered; dynamic smem (51456 B).
__global__ void __launch_bounds__(WPB*32) scanOut() {
    extern __shared__ float dyn[];
    float (*wbuf)[2][8][32] = (float(*)[2][8][32])(dyn);
    float (*vbuf)[2][8][32] = (float(*)[2][8][32])(dyn + 2048);
    float (*kbuf)[2][8][32] = (float(*)[2][8][32])(dyn + 4096);
    float (*qbuf)[2][8][32] = (float(*)[2][8][32])(dyn + 6144);
    float (*part)[32][36]   = (float(*)[32][36])(dyn + 8192);
    float (*bbuf)[2][8]     = (float(*)[2][8])(dyn + 8192 + WPB*32*36);

    const int wid  = threadIdx.x >> 5;
    const int lane = threadIdx.x & 31;
    const int wg   = blockIdx.x * WPB + wid;
    const int bh   = wg >> 6;
    const int c    = wg & 63;
    const int b = bh >> 3, h = bh & 7;
    const size_t sbase = ((size_t)bh * Tq + (size_t)c * LCH) * 32;
    const size_t bbase = (size_t)bh * Tq + (size_t)c * LCH;
    const size_t s0base = ((size_t)bh * CCH + c) * 1024 + (size_t)lane * 32;
    const int rowbase = b * Tq + c * LCH;

    auto issue = [&](int wnd, int bf) {
        size_t goff = sbase + (size_t)wnd * 256;
        uint32_t dw = s2u(&wbuf[wid][bf][0][0]);
        uint32_t dv = s2u(&vbuf[wid][bf][0][0]);
        uint32_t dk = s2u(&kbuf[wid][bf][0][0]);
        uint32_t dq = s2u(&qbuf[wid][bf][0][0]);
#pragma unroll
        for (int i = 0; i < 2; ++i) {
            int e4 = i * 32 + lane;
            asm volatile("cp.async.cg.shared.global [%0], [%1], 16;"
                         :: "r"(dw + e4*16u), "l"((const float4*)(g_w + goff) + e4));
            asm volatile("cp.async.cg.shared.global [%0], [%1], 16;"
                         :: "r"(dv + e4*16u), "l"((const float4*)(g_v + goff) + e4));
            asm volatile("cp.async.cg.shared.global [%0], [%1], 16;"
                         :: "r"(dk + e4*16u), "l"((const float4*)(g_k + goff) + e4));
            asm volatile("cp.async.cg.shared.global [%0], [%1], 16;"
                         :: "r"(dq + e4*16u), "l"((const float4*)(g_q + goff) + e4));
        }
        if (lane < 8) {
            uint32_t db = s2u(&bbuf[wid][bf][lane]);
            asm volatile("cp.async.ca.shared.global [%0], [%1], 4;"
                         :: "r"(db), "l"(g_beta + bbase + wnd * 8 + lane));
        }
        asm volatile("cp.async.commit_group;");
    };

    issue(0, 0);
    issue(1, 1);
    asm volatile("cp.async.wait_group 1;" ::: "memory");
    __syncwarp();

    float S[32];
#pragma unroll
    for (int j = 0; j < 8; ++j) {
        float4 s0 = *(const float4*)&g_S0[s0base + 4*j];
        S[4*j] = s0.x; S[4*j+1] = s0.y; S[4*j+2] = s0.z; S[4*j+3] = s0.w;
    }

    for (int w = 0; w < 8; ++w) {
        const int cur = w & 1;
#pragma unroll
        for (int t = 0; t < 8; ++t) {
            const float4* w4p = (const float4*)&wbuf[wid][cur][t][0];
            const float4* v4p = (const float4*)&vbuf[wid][cur][t][0];
            float k    = kbuf[wid][cur][t][lane];
            float q    = qbuf[wid][cur][t][lane];
            float beta = bbuf[wid][cur][t];
            float a0 = 0.f, a1 = 0.f, a2 = 0.f, a3 = 0.f;
            float4 w4[8];
#pragma unroll
            for (int j = 0; j < 8; ++j) {
                w4[j] = w4p[j];
                a0 = fmaf(S[4*j+0], w4[j].x, a0);
                a1 = fmaf(S[4*j+1], w4[j].y, a1);
                a2 = fmaf(S[4*j+2], w4[j].z, a2);
                a3 = fmaf(S[4*j+3], w4[j].w, a3);
            }
            float cs = -beta * ((a0 + a1) + (a2 + a3));
#pragma unroll
            for (int j = 0; j < 8; ++j) {
                float4 v4 = v4p[j];
                S[4*j+0] = fmaf(cs, w4[j].x, fmaf(k, v4.x, S[4*j+0]));
                S[4*j+1] = fmaf(cs, w4[j].y, fmaf(k, v4.y, S[4*j+1]));
                S[4*j+2] = fmaf(cs, w4[j].z, fmaf(k, v4.z, S[4*j+2]));
                S[4*j+3] = fmaf(cs, w4[j].w, fmaf(k, v4.w, S[4*j+3]));
            }
#pragma unroll
            for (int j = 0; j < 8; ++j) {
                *(float4*)&part[wid][lane][4*j] =
                    make_float4(q * S[4*j], q * S[4*j+1], q * S[4*j+2], q * S[4*j+3]);
            }
            __syncwarp();
            float o0 = 0.f, o1 = 0.f, o2 = 0.f, o3 = 0.f;
#pragma unroll
            for (int dd = 0; dd < 32; dd += 4) {
                o0 += part[wid][dd+0][lane];
                o1 += part[wid][dd+1][lane];
                o2 += part[wid][dd+2][lane];
                o3 += part[wid][dd+3][lane];
            }
            float o = (o0 + o1) + (o2 + o3);
            size_t oidx = (size_t)(rowbase + w * 8 + t) * 256 + h * 32 + lane;
            __nv_bfloat16 hi, lo;
            bf16split(o, hi, lo);
            g_atth[oidx] = hi; g_attl[oidx] = lo;
            __syncwarp();
        }
        if (w < 6) {
            __syncwarp();
            issue(w + 2, cur);
            asm volatile("cp.async.wait_group 1;" ::: "memory");
            __syncwarp();
        } else if (w == 6) {
            asm volatile("cp.async.wait_group 0;" ::: "memory");
            __syncwarp();
        }
    }
}

// -------------------- launch --------------------
extern "C" void kernel_launch(void* const* d_in, const int* in_sizes, int n_in,
                              void* d_out, int out_size) {
    const float* x     = (const float*)d_in[0];
    const float* Wq    = (const float*)d_in[1];
    const float* Wk    = (const float*)d_in[2];
    const float* Wv    = (const float*)d_in[3];
    const float* Ww    = (const float*)d_in[4];
    const float* Wbeta = (const float*)d_in[5];
    const float* bbeta = (const float*)d_in[6];
    const float* Wg    = (const float*)d_in[7];
    const float* bg    = (const float*)d_in[8];
    const float* Wo    = (const float*)d_in[9];
    float* out = (float*)d_out;

    void *pXh, *pXl, *pWh, *pWl, *pAh, *pAl, *pWoh, *pWol;
    cudaGetSymbolAddress(&pXh,  g_xh);
    cudaGetSymbolAddress(&pXl,  g_xl);
    cudaGetSymbolAddress(&pWh,  g_Wh);
    cudaGetSymbolAddress(&pWl,  g_Wl);
    cudaGetSymbolAddress(&pAh,  g_atth);
    cudaGetSymbolAddress(&pAl,  g_attl);
    cudaGetSymbolAddress(&pWoh, g_woh);
    cudaGetSymbolAddress(&pWol, g_wol);

    const int SMEM = 3 * 4 * 128 * 32 * 2;   // 98304 bytes (3 swizzled 32KB stages)
    cudaFuncSetAttribute(hgemm3, cudaFuncAttributeMaxDynamicSharedMemorySize, SMEM);
    const int SCAN_SMEM = (8192 + WPB*32*36 + WPB*2*8) * 4;   // 51456 bytes
    cudaFuncSetAttribute(scanOut, cudaFuncAttributeMaxDynamicSharedMemorySize, SCAN_SMEM);

    // 1) fused conversions: pack/split W, split x, split Wo
    cvtAll<<<10784, 256>>>(x, Wq, Wk, Wv, Ww, Wbeta, Wg, Wo);

    // 2) projection GEMM + activations, scattering straight into SoA streams (mode 1)
    hgemm3<<<dim3(NCP / 128, MROWS / 128), 256, SMEM>>>(
        (const __nv_bfloat16*)pXh, (const __nv_bfloat16*)pXl,
        (const __nv_bfloat16*)pWh, (const __nv_bfloat16*)pWl,
        nullptr, NC, HIDq, 1, bbeta, bg);

    // 3) normalize w in-stream, fold q*scale*eg in-stream
    prep<<<16384, 256>>>();

    // 4) chunked associative scan over the recurrence
    scanPA<<<(BH * CCH) / WPB, WPB * 32>>>();
    combine<<<BH, 1024>>>();
    scanOut<<<(BH * CCH) / WPB, WPB * 32, SCAN_SMEM>>>();

    // 5) output projection: out[16384,512] = att @ Wo^T (mode 0, row-major)
    hgemm3<<<dim3(HIDq / 128, MROWS / 128), 256, SMEM>>>(
        (const __nv_bfloat16*)pAh, (const __nv_bfloat16*)pAl,
        (const __nv_bfloat16*)pWoh, (const __nv_bfloat16*)pWol,
        out, HIDq, Hh * Dd, 0, nullptr, nullptr);
}

// round 17
// speedup vs baseline: 1.0860x; 1.0268x over previous
#include <cuda_runtime.h>
#include <cuda_bf16.h>
#include <cstdint>
#include <math.h>

// Problem constants
#define Bq   4
#define Tq   4096
#define Hh   8
#define Dd   32
#define HIDq 512
#define NC   1040            // packed projection columns: q256 k256 v256 w256 beta8 g8
#define NCP  1152            // NC padded to multiple of 128
#define MROWS (Bq*Tq)        // 16384
#define BH   (Bq*Hh)         // 32
#define CCH  64              // chunks
#define LCH  64              // steps per chunk
#define WPB  4               // warps per block in scan kernels

// -------------------- scratch (device globals; zero-initialized, no allocation) ----
__device__ __nv_bfloat16  g_Wh[(size_t)NCP * HIDq];       // packed weights hi (pad rows zero)
__device__ __nv_bfloat16  g_Wl[(size_t)NCP * HIDq];       // packed weights lo
__device__ __nv_bfloat16  g_xh[(size_t)MROWS * HIDq];     // x hi (16 MB)
__device__ __nv_bfloat16  g_xl[(size_t)MROWS * HIDq];     // x lo
__device__ __nv_bfloat16  g_woh[(size_t)HIDq * 256];      // Wo hi
__device__ __nv_bfloat16  g_wol[(size_t)HIDq * 256];      // Wo lo
__device__ __nv_bfloat16  g_atth[(size_t)MROWS * 256];    // attention out hi (8 MB)
__device__ __nv_bfloat16  g_attl[(size_t)MROWS * 256];    // attention out lo
__device__ float  g_w[(size_t)BH * Tq * Dd];              // raw w (SoA streams)
__device__ float  g_v[(size_t)BH * Tq * Dd];
__device__ float  g_k[(size_t)BH * Tq * Dd];
__device__ float  g_q[(size_t)BH * Tq * Dd];              // raw q
__device__ float  g_eg[(size_t)BH * Tq];                  // sigmoid(zg+bg)
__device__ float  g_beta[(size_t)BH * Tq];                // beta (sigmoid applied)
__device__ float  g_P [(size_t)BH * CCH * 1024];          // chunk transfer matrices
__device__ float  g_A [(size_t)BH * CCH * 1024];          // chunk injections
__device__ float  g_S0[(size_t)BH * CCH * 1024];          // state at chunk starts

// -------------------- helpers --------------------
__device__ __forceinline__ void bf16split(float v, __nv_bfloat16& hi, __nv_bfloat16& lo) {
    hi = __float2bfloat16(v);
    lo = __float2bfloat16(v - __bfloat162float(hi));
}

__device__ __forceinline__ void ldsm4(uint32_t& r0, uint32_t& r1, uint32_t& r2, uint32_t& r3,
                                      uint32_t addr) {
    asm volatile("ldmatrix.sync.aligned.m8n8.x4.shared.b16 {%0,%1,%2,%3}, [%4];"
        : "=r"(r0), "=r"(r1), "=r"(r2), "=r"(r3) : "r"(addr));
}

__device__ __forceinline__ void mma_bf16(float* d, uint32_t a0, uint32_t a1, uint32_t a2,
                                         uint32_t a3, uint32_t b0, uint32_t b1) {
    asm volatile("mma.sync.aligned.m16n8k16.row.col.f32.bf16.bf16.f32 "
        "{%0,%1,%2,%3}, {%4,%5,%6,%7}, {%8,%9}, {%0,%1,%2,%3};"
        : "+f"(d[0]), "+f"(d[1]), "+f"(d[2]), "+f"(d[3])
        : "r"(a0), "r"(a1), "r"(a2), "r"(a3), "r"(b0), "r"(b1));
}

// swizzled smem byte offset within one 128x32 bf16 array: row stride 64B, 4 chunks of 16B
__device__ __forceinline__ uint32_t swz(int row, int col) {
    uint32_t chunk = (uint32_t)(col >> 3);
    return (uint32_t)(row * 64) + ((chunk ^ (((uint32_t)row >> 1) & 3u)) << 4);
}

__device__ __forceinline__ uint32_t s2u(const void* p) {
    return (uint32_t)__cvta_generic_to_shared(p);
}

// -------------------- fused conversions: pack/split W, split x, split Wo ------------
// blockIdx ranges: [0,2080) packW, [2080,10272) cvtA, [10272,10784) cvtWo
__global__ void __launch_bounds__(256) cvtAll(
        const float* __restrict__ x,
        const float* __restrict__ wq, const float* __restrict__ wk,
        const float* __restrict__ wv, const float* __restrict__ ww,
        const float* __restrict__ wb, const float* __restrict__ wg,
        const float* __restrict__ Wo) {
    int b = blockIdx.x;
    if (b < 2080) {
        int i = b * 256 + threadIdx.x;           // 0 .. 532479
        int r = i >> 9, c = i & 511;
        float v;
        if      (r < 256)  v = wq[i];
        else if (r < 512)  v = wk[(r - 256)  * HIDq + c];
        else if (r < 768)  v = wv[(r - 512)  * HIDq + c];
        else if (r < 1024) v = ww[(r - 768)  * HIDq + c];
        else if (r < 1032) v = wb[(r - 1024) * HIDq + c];
        else               v = wg[(r - 1032) * HIDq + c];
        __nv_bfloat16 hi, lo;
        bf16split(v, hi, lo);
        g_Wh[i] = hi; g_Wl[i] = lo;
    } else if (b < 10272) {
        int i = (b - 2080) * 256 + threadIdx.x;  // float4 index, 2097152 total
        float4 v = ((const float4*)x)[i];
        __nv_bfloat16 h0, l0, h1, l1, h2, l2, h3, l3;
        bf16split(v.x, h0, l0); bf16split(v.y, h1, l1);
        bf16split(v.z, h2, l2); bf16split(v.w, h3, l3);
        ((__nv_bfloat162*)g_xh)[2*i]   = __halves2bfloat162(h0, h1);
        ((__nv_bfloat162*)g_xh)[2*i+1] = __halves2bfloat162(h2, h3);
        ((__nv_bfloat162*)g_xl)[2*i]   = __halves2bfloat162(l0, l1);
        ((__nv_bfloat162*)g_xl)[2*i+1] = __halves2bfloat162(l2, l3);
    } else {
        int i = (b - 10272) * 256 + threadIdx.x; // 0 .. 131071
        __nv_bfloat16 hi, lo;
        bf16split(Wo[i], hi, lo);
        g_woh[i] = hi; g_wol[i] = lo;
    }
}

// -------------------- tensor-core GEMM: 3-term bf16 split, 128x128x32, 8 warps ------
// mode 0: plain row-major store to C (ldC = Nreal).
// mode 1: scatter q/k/v/w into SoA streams; beta/g sigmoids into g_beta/g_eg.
__global__ void __launch_bounds__(256, 2)
hgemm3(const __nv_bfloat16* __restrict__ Ahp, const __nv_bfloat16* __restrict__ Alp,
       const __nv_bfloat16* __restrict__ Bhp, const __nv_bfloat16* __restrict__ Blp,
       float* __restrict__ C, int Nreal, int K, int mode,
       const float* __restrict__ bbeta, const float* __restrict__ bg) {
    extern __shared__ __nv_bfloat16 smem[];   // 3 stages * 4 arrays * 128*32 bf16 = 96KB
    const int tid  = threadIdx.x;
    const int wid  = tid >> 5, lane = tid & 31;
    const int m0 = blockIdx.y * 128, n0 = blockIdx.x * 128;
    const int wm = (wid >> 2) * 64, wn = (wid & 3) * 32;
    const bool active = (n0 + wn) < Nreal;
    const uint32_t sbase = s2u(&smem[0]);

    const __nv_bfloat16* gsrc[4];
    gsrc[0] = Ahp + (size_t)m0 * K;
    gsrc[1] = Alp + (size_t)m0 * K;
    gsrc[2] = Bhp + (size_t)n0 * K;
    gsrc[3] = Blp + (size_t)n0 * K;

    float acc[4][4][4];
#pragma unroll
    for (int mi = 0; mi < 4; ++mi)
#pragma unroll
        for (int nj = 0; nj < 4; ++nj)
#pragma unroll
            for (int cc = 0; cc < 4; ++cc) acc[mi][nj][cc] = 0.f;

    auto load_stage = [&](int s, int kt) {
#pragma unroll
        for (int arr = 0; arr < 4; ++arr) {
            uint32_t abase = sbase + (uint32_t)s * 32768u + (uint32_t)arr * 8192u;
            const __nv_bfloat16* src = gsrc[arr];
#pragma unroll
            for (int i = 0; i < 2; ++i) {
                int lin = i * 256 + tid;
                int r = lin >> 2, c = lin & 3;
                uint32_t dst = abase + swz(r, c * 8);
                const void* sp = src + (size_t)r * K + kt + c * 8;
                asm volatile("cp.async.cg.shared.global [%0], [%1], 16;" :: "r"(dst), "l"(sp));
            }
        }
        asm volatile("cp.async.commit_group;");
    };

    const int KT = K / 32;
    load_stage(0, 0);
    if (KT > 1) load_stage(1, 32);

    for (int it = 0; it < KT; ++it) {
        if (it + 1 < KT) {
            asm volatile("cp.async.wait_group 1;");
        } else {
            asm volatile("cp.async.wait_group 0;");
        }
        __syncthreads();   // single barrier: stage it%3 visible AND iter it-1 reads done
        if (it + 2 < KT) load_stage((it + 2) % 3, (it + 2) * 32);

        if (active) {
            const uint32_t stg = sbase + (uint32_t)(it % 3) * 32768u;
            const uint32_t aHs = stg;
            const uint32_t aLs = stg + 8192u;
            const uint32_t bHs = stg + 16384u;
            const uint32_t bLs = stg + 24576u;

#pragma unroll
            for (int kk = 0; kk < 32; kk += 16) {
                uint32_t fbh[4][2], fbl[4][2];
#pragma unroll
                for (int j = 0; j < 2; ++j) {
                    int row = wn + j * 16 + (lane & 7) + ((lane >> 4) & 1) * 8;
                    int col = kk + ((lane >> 3) & 1) * 8;
                    uint32_t off = swz(row, col);
                    uint32_t t0, t1, t2, t3;
                    ldsm4(t0, t1, t2, t3, bHs + off);
                    fbh[j*2][0] = t0; fbh[j*2][1] = t1; fbh[j*2+1][0] = t2; fbh[j*2+1][1] = t3;
                    ldsm4(t0, t1, t2, t3, bLs + off);
                    fbl[j*2][0] = t0; fbl[j*2][1] = t1; fbl[j*2+1][0] = t2; fbl[j*2+1][1] = t3;
                }
#pragma unroll
                for (int mi = 0; mi < 4; ++mi) {
                    int row = wm + mi * 16 + (lane & 7) + ((lane >> 3) & 1) * 8;
                    int col = kk + ((lane >> 4) & 1) * 8;
                    uint32_t off = swz(row, col);
                    uint32_t ah0, ah1, ah2, ah3, al0, al1, al2, al3;
                    ldsm4(ah0, ah1, ah2, ah3, aHs + off);
                    ldsm4(al0, al1, al2, al3, aLs + off);
#pragma unroll
                    for (int nj = 0; nj < 4; ++nj)
                        mma_bf16(acc[mi][nj], ah0, ah1, ah2, ah3, fbh[nj][0], fbh[nj][1]);
#pragma unroll
                    for (int nj = 0; nj < 4; ++nj)
                        mma_bf16(acc[mi][nj], ah0, ah1, ah2, ah3, fbl[nj][0], fbl[nj][1]);
#pragma unroll
                    for (int nj = 0; nj < 4; ++nj)
                        mma_bf16(acc[mi][nj], al0, al1, al2, al3, fbh[nj][0], fbh[nj][1]);
                }
            }
        }
    }

    const int grp = lane >> 2, t2c = (lane & 3) << 1;
    if (mode == 0) {
#pragma unroll
        for (int mi = 0; mi < 4; ++mi) {
#pragma unroll
            for (int nj = 0; nj < 4; ++nj) {
                int gm = m0 + wm + mi * 16 + grp;
                int gn = n0 + wn + nj * 8 + t2c;
                float* p0 = C + (size_t)gm * Nreal + gn;
                float* p1 = C + (size_t)(gm + 8) * Nreal + gn;
                p0[0] = acc[mi][nj][0]; p0[1] = acc[mi][nj][1];
                p1[0] = acc[mi][nj][2]; p1[1] = acc[mi][nj][3];
            }
        }
    } else {
#pragma unroll
        for (int mi = 0; mi < 4; ++mi) {
#pragma unroll
            for (int nj = 0; nj < 4; ++nj) {
                int gm = m0 + wm + mi * 16 + grp;
                int gn = n0 + wn + nj * 8 + t2c;
                int b = gm >> 12, t = gm & 4095;
                float v0 = acc[mi][nj][0], v1 = acc[mi][nj][1];
                float v2 = acc[mi][nj][2], v3 = acc[mi][nj][3];
                if (gn < 1024) {
                    int arr = gn >> 8, h = (gn >> 5) & 7, d = gn & 31;
                    float* dst = (arr == 0) ? g_q : (arr == 1) ? g_k
                               : (arr == 2) ? g_v : g_w;
                    size_t i0 = (((size_t)(b * 8 + h) * Tq + t) << 5) + d;
                    *(float2*)&dst[i0]       = make_float2(v0, v1);
                    *(float2*)&dst[i0 + 256] = make_float2(v2, v3);   // t+8
                } else if (gn < 1032) {
                    int h = gn - 1024;
                    size_t i0 = (size_t)(b * 8 + h)     * Tq + t;
                    size_t i1 = (size_t)(b * 8 + h + 1) * Tq + t;
                    g_beta[i0]     = 2.f / (1.f + expf(-(v0 + bbeta[h])));
                    g_beta[i1]     = 2.f / (1.f + expf(-(v1 + bbeta[h + 1])));
                    g_beta[i0 + 8] = 2.f / (1.f + expf(-(v2 + bbeta[h])));
                    g_beta[i1 + 8] = 2.f / (1.f + expf(-(v3 + bbeta[h + 1])));
                } else if (gn < 1040) {
                    int h = gn - 1032;
                    size_t i0 = (size_t)(b * 8 + h)     * Tq + t;
                    size_t i1 = (size_t)(b * 8 + h + 1) * Tq + t;
                    g_eg[i0]     = 1.f / (1.f + expf(-(v0 + bg[h])));
                    g_eg[i1]     = 1.f / (1.f + expf(-(v1 + bg[h + 1])));
                    g_eg[i0 + 8] = 1.f / (1.f + expf(-(v2 + bg[h])));
                    g_eg[i1 + 8] = 1.f / (1.f + expf(-(v3 + bg[h + 1])));
                }
                // gn >= 1040: padding, discard
            }
        }
    }
}

// -------------------- pass1: per-chunk transfer matrix P and injection A --------------------
// cp.async double-buffered SoA windows; w-normalization folded in as beta_eff.
__global__ void __launch_bounds__(WPB*32) scanPA() {
    __shared__ float wbuf[WPB][2][8][32];
    __shared__ float vbuf[WPB][2][8][32];
    __shared__ float kbuf[WPB][2][8][32];
    __shared__ float bbuf[WPB][2][8];

    const int wid  = threadIdx.x >> 5;
    const int lane = threadIdx.x & 31;
    const int wg   = blockIdx.x * WPB + wid;
    const int bh   = wg >> 6;
    const int c    = wg & 63;
    const size_t sbase = ((size_t)bh * Tq + (size_t)c * LCH) * 32;
    const size_t bbase = (size_t)bh * Tq + (size_t)c * LCH;

    auto issue = [&](int wnd, int bf) {
        size_t goff = sbase + (size_t)wnd * 256;
        uint32_t dw = s2u(&wbuf[wid][bf][0][0]);
        uint32_t dv = s2u(&vbuf[wid][bf][0][0]);
        uint32_t dk = s2u(&kbuf[wid][bf][0][0]);
#pragma unroll
        for (int i = 0; i < 2; ++i) {
            int e4 = i * 32 + lane;
            const void* sw = (const float4*)(g_w + goff) + e4;
            const void* sv = (const float4*)(g_v + goff) + e4;
            const void* sk = (const float4*)(g_k + goff) + e4;
            asm volatile("cp.async.cg.shared.global [%0], [%1], 16;" :: "r"(dw + e4*16u), "l"(sw));
            asm volatile("cp.async.cg.shared.global [%0], [%1], 16;" :: "r"(dv + e4*16u), "l"(sv));
            asm volatile("cp.async.cg.shared.global [%0], [%1], 16;" :: "r"(dk + e4*16u), "l"(sk));
        }
        if (lane < 8) {
            uint32_t db = s2u(&bbuf[wid][bf][lane]);
            asm volatile("cp.async.ca.shared.global [%0], [%1], 4;"
                         :: "r"(db), "l"(g_beta + bbase + wnd * 8 + lane));
        }
        asm volatile("cp.async.commit_group;");
    };

    issue(0, 0);
    issue(1, 1);
    asm volatile("cp.async.wait_group 1;" ::: "memory");
    __syncwarp();

    float P[32], A[32];
#pragma unroll
    for (int m = 0; m < 32; ++m) { P[m] = (m == lane) ? 1.f : 0.f; A[m] = 0.f; }

    for (int w = 0; w < 8; ++w) {
        const int cur = w & 1;
        // fold w-normalization into beta: beta_eff = beta / (||w||+1e-6)^2
        {
            int tt = lane >> 2, qd = lane & 3;
            const float4* wp = (const float4*)&wbuf[wid][cur][tt][0];
            float4 ax = wp[qd * 2], bx = wp[qd * 2 + 1];
            float s8 = ax.x*ax.x + ax.y*ax.y + ax.z*ax.z + ax.w*ax.w
                     + bx.x*bx.x + bx.y*bx.y + bx.z*bx.z + bx.w*bx.w;
            s8 += __shfl_xor_sync(0xffffffffu, s8, 1);
            s8 += __shfl_xor_sync(0xffffffffu, s8, 2);
            float nrm = sqrtf(s8) + 1e-6f;
            float be = bbuf[wid][cur][tt] / (nrm * nrm);
            __syncwarp();
            if (qd == 0) bbuf[wid][cur][tt] = be;
            __syncwarp();
        }
#pragma unroll
        for (int t = 0; t < 8; ++t) {
            const float4* w4p = (const float4*)&wbuf[wid][cur][t][0];
            const float4* v4p = (const float4*)&vbuf[wid][cur][t][0];
            float k    = kbuf[wid][cur][t][lane];
            float beta = bbuf[wid][cur][t];
            float p0 = 0.f, p1 = 0.f, p2 = 0.f, p3 = 0.f;
            float a0 = 0.f, a1 = 0.f, a2 = 0.f, a3 = 0.f;
            float4 w4[8];
#pragma unroll
            for (int j = 0; j < 8; ++j) {
                w4[j] = w4p[j];
                p0 = fmaf(P[4*j+0], w4[j].x, p0);
                p1 = fmaf(P[4*j+1], w4[j].y, p1);
                p2 = fmaf(P[4*j+2], w4[j].z, p2);
                p3 = fmaf(P[4*j+3], w4[j].w, p3);
                a0 = fmaf(A[4*j+0], w4[j].x, a0);
                a1 = fmaf(A[4*j+1], w4[j].y, a1);
                a2 = fmaf(A[4*j+2], w4[j].z, a2);
                a3 = fmaf(A[4*j+3], w4[j].w, a3);
            }
            float cp = -beta * ((p0 + p1) + (p2 + p3));
            float ca = -beta * ((a0 + a1) + (a2 + a3));
#pragma unroll
            for (int j = 0; j < 8; ++j) {
                float4 v4 = v4p[j];
                P[4*j+0] = fmaf(cp, w4[j].x, P[4*j+0]);
                P[4*j+1] = fmaf(cp, w4[j].y, P[4*j+1]);
                P[4*j+2] = fmaf(cp, w4[j].z, P[4*j+2]);
                P[4*j+3] = fmaf(cp, w4[j].w, P[4*j+3]);
                A[4*j+0] = fmaf(ca, w4[j].x, fmaf(k, v4.x, A[4*j+0]));
                A[4*j+1] = fmaf(ca, w4[j].y, fmaf(k, v4.y, A[4*j+1]));
                A[4*j+2] = fmaf(ca, w4[j].z, fmaf(k, v4.z, A[4*j+2]));
                A[4*j+3] = fmaf(ca, w4[j].w, fmaf(k, v4.w, A[4*j+3]));
            }
        }
        if (w < 6) {
            __syncwarp();
            issue(w + 2, cur);
            asm volatile("cp.async.wait_group 1;" ::: "memory");
            __syncwarp();
        } else if (w == 6) {
            asm volatile("cp.async.wait_group 0;" ::: "memory");
            __syncwarp();
        }
    }

    size_t obase = ((size_t)bh * CCH + c) * 1024 + (size_t)lane * 32;
#pragma unroll
    for (int j = 0; j < 8; ++j) {
        *(float4*)&g_P[obase + 4*j] = make_float4(P[4*j], P[4*j+1], P[4*j+2], P[4*j+3]);
        *(float4*)&g_A[obase + 4*j] = make_float4(A[4*j], A[4*j+1], A[4*j+2], A[4*j+3]);
    }
}

// -------------------- combine: sequential chunk-boundary states --------------------
__global__ void __launch_bounds__(1024, 1) combine() {
    __shared__ float Ssh[32][32];
    const int bh = blockIdx.x;
    const int tid = threadIdx.x;
    const int d = tid >> 5, m = tid & 31;

    float s = 0.f;
    for (int c = 0; c < CCH; ++c) {
        size_t base = ((size_t)bh * CCH + c) * 1024;
        g_S0[base + tid] = s;
        Ssh[d][m] = s;
        __syncthreads();
        float acc = g_A[base + tid];
        const float* Pc = g_P + base;
#pragma unroll
        for (int mm = 0; mm < 32; ++mm)
            acc = fmaf(Ssh[d][mm], Pc[mm * 32 + m], acc);
        __syncthreads();
        s = acc;
    }
}

// -------------------- pass2: replay chunks, emit outputs as bf16 hi/lo ----------------
// cp.async double-buffered; norm folded as beta_eff; out scaled by scale*eg.
__global__ void __launch_bounds__(WPB*32) scanOut() {
    extern __shared__ float dyn[];
    float (*wbuf)[2][8][32] = (float(*)[2][8][32])(dyn);
    float (*vbuf)[2][8][32] = (float(*)[2][8][32])(dyn + 2048);
    float (*kbuf)[2][8][32] = (float(*)[2][8][32])(dyn + 4096);
    float (*qbuf)[2][8][32] = (float(*)[2][8][32])(dyn + 6144);
    float (*part)[32][36]   = (float(*)[32][36])(dyn + 8192);
    float (*bbuf)[2][8]     = (float(*)[2][8])(dyn + 8192 + WPB*32*36);
    float (*ebuf)[2][8]     = (float(*)[2][8])(dyn + 8192 + WPB*32*36 + WPB*2*8);

    const int wid  = threadIdx.x >> 5;
    const int lane = threadIdx.x & 31;
    const int wg   = blockIdx.x * WPB + wid;
    const int bh   = wg >> 6;
    const int c    = wg & 63;
    const int b = bh >> 3, h = bh & 7;
    const size_t sbase = ((size_t)bh * Tq + (size_t)c * LCH) * 32;
    const size_t bbase = (size_t)bh * Tq + (size_t)c * LCH;
    const size_t s0base = ((size_t)bh * CCH + c) * 1024 + (size_t)lane * 32;
    const int rowbase = b * Tq + c * LCH;

    auto issue = [&](int wnd, int bf) {
        size_t goff = sbase + (size_t)wnd * 256;
        uint32_t dw = s2u(&wbuf[wid][bf][0][0]);
        uint32_t dv = s2u(&vbuf[wid][bf][0][0]);
        uint32_t dk = s2u(&kbuf[wid][bf][0][0]);
        uint32_t dq = s2u(&qbuf[wid][bf][0][0]);
#pragma unroll
        for (int i = 0; i < 2; ++i) {
            int e4 = i * 32 + lane;
            asm volatile("cp.async.cg.shared.global [%0], [%1], 16;"
                         :: "r"(dw + e4*16u), "l"((const float4*)(g_w + goff) + e4));
            asm volatile("cp.async.cg.shared.global [%0], [%1], 16;"
                         :: "r"(dv + e4*16u), "l"((const float4*)(g_v + goff) + e4));
            asm volatile("cp.async.cg.shared.global [%0], [%1], 16;"
                         :: "r"(dk + e4*16u), "l"((const float4*)(g_k + goff) + e4));
            asm volatile("cp.async.cg.shared.global [%0], [%1], 16;"
                         :: "r"(dq + e4*16u), "l"((const float4*)(g_q + goff) + e4));
        }
        if (lane < 8) {
            uint32_t db = s2u(&bbuf[wid][bf][lane]);
            asm volatile("cp.async.ca.shared.global [%0], [%1], 4;"
                         :: "r"(db), "l"(g_beta + bbase + wnd * 8 + lane));
        } else if (lane < 16) {
            uint32_t de = s2u(&ebuf[wid][bf][lane - 8]);
            asm volatile("cp.async.ca.shared.global [%0], [%1], 4;"
                         :: "r"(de), "l"(g_eg + bbase + wnd * 8 + (lane - 8)));
        }
        asm volatile("cp.async.commit_group;");
    };

    issue(0, 0);
    issue(1, 1);
    asm volatile("cp.async.wait_group 1;" ::: "memory");
    __syncwarp();

    float S[32];
#pragma unroll
    for (int j = 0; j < 8; ++j) {
        float4 s0 = *(const float4*)&g_S0[s0base + 4*j];
        S[4*j] = s0.x; S[4*j+1] = s0.y; S[4*j+2] = s0.z; S[4*j+3] = s0.w;
    }

    const float scale = 0.17677669529663687f;   // 32^-0.5
    for (int w = 0; w < 8; ++w) {
        const int cur = w & 1;
        // fold w-normalization into beta: beta_eff = beta / (||w||+1e-6)^2
        {
            int tt = lane >> 2, qd = lane & 3;
            const float4* wp = (const float4*)&wbuf[wid][cur][tt][0];
            float4 ax = wp[qd * 2], bx = wp[qd * 2 + 1];
            float s8 = ax.x*ax.x + ax.y*ax.y + ax.z*ax.z + ax.w*ax.w
                     + bx.x*bx.x + bx.y*bx.y + bx.z*bx.z + bx.w*bx.w;
            s8 += __shfl_xor_sync(0xffffffffu, s8, 1);
            s8 += __shfl_xor_sync(0xffffffffu, s8, 2);
            float nrm = sqrtf(s8) + 1e-6f;
            float be = bbuf[wid][cur][tt] / (nrm * nrm);
            __syncwarp();
            if (qd == 0) bbuf[wid][cur][tt] = be;
            __syncwarp();
        }
#pragma unroll
        for (int t = 0; t < 8; ++t) {
            const float4* w4p = (const float4*)&wbuf[wid][cur][t][0];
            const float4* v4p = (const float4*)&vbuf[wid][cur][t][0];
            float k    = kbuf[wid][cur][t][lane];
            float q    = qbuf[wid][cur][t][lane];
            float beta = bbuf[wid][cur][t];
            float a0 = 0.f, a1 = 0.f, a2 = 0.f, a3 = 0.f;
            float4 w4[8];
#pragma unroll
            for (int j = 0; j < 8; ++j) {
                w4[j] = w4p[j];
                a0 = fmaf(S[4*j+0], w4[j].x, a0);
                a1 = fmaf(S[4*j+1], w4[j].y, a1);
                a2 = fmaf(S[4*j+2], w4[j].z, a2);
                a3 = fmaf(S[4*j+3], w4[j].w, a3);
            }
            float cs = -beta * ((a0 + a1) + (a2 + a3));
#pragma unroll
            for (int j = 0; j < 8; ++j) {
                float4 v4 = v4p[j];
                S[4*j+0] = fmaf(cs, w4[j].x, fmaf(k, v4.x, S[4*j+0]));
                S[4*j+1] = fmaf(cs, w4[j].y, fmaf(k, v4.y, S[4*j+1]));
                S[4*j+2] = fmaf(cs, w4[j].z, fmaf(k, v4.z, S[4*j+2]));
                S[4*j+3] = fmaf(cs, w4[j].w, fmaf(k, v4.w, S[4*j+3]));
            }
#pragma unroll
            for (int j = 0; j < 8; ++j) {
                *(float4*)&part[wid][lane][4*j] =
                    make_float4(q * S[4*j], q * S[4*j+1], q * S[4*j+2], q * S[4*j+3]);
            }
            __syncwarp();
            float o0 = 0.f, o1 = 0.f, o2 = 0.f, o3 = 0.f;
#pragma unroll
            for (int dd = 0; dd < 32; dd += 4) {
                o0 += part[wid][dd+0][lane];
                o1 += part[wid][dd+1][lane];
                o2 += part[wid][dd+2][lane];
                o3 += part[wid][dd+3][lane];
            }
            float o = ((o0 + o1) + (o2 + o3)) * (scale * ebuf[wid][cur][t]);
            size_t oidx = (size_t)(rowbase + w * 8 + t) * 256 + h * 32 + lane;
            __nv_bfloat16 hi, lo;
            bf16split(o, hi, lo);
            g_atth[oidx] = hi; g_attl[oidx] = lo;
            __syncwarp();
        }
        if (w < 6) {
            __syncwarp();
            issue(w + 2, cur);
            asm volatile("cp.async.wait_group 1;" ::: "memory");
            __syncwarp();
        } else if (w == 6) {
            asm volatile("cp.async.wait_group 0;" ::: "memory");
            __syncwarp();
        }
    }
}

// -------------------- launch --------------------
extern "C" void kernel_launch(void* const* d_in, const int* in_sizes, int n_in,
                              void* d_out, int out_size) {
    const float* x     = (const float*)d_in[0];
    const float* Wq    = (const float*)d_in[1];
    const float* Wk    = (const float*)d_in[2];
    const float* Wv    = (const float*)d_in[3];
    const float* Ww    = (const float*)d_in[4];
    const float* Wbeta = (const float*)d_in[5];
    const float* bbeta = (const float*)d_in[6];
    const float* Wg    = (const float*)d_in[7];
    const float* bg    = (const float*)d_in[8];
    const float* Wo    = (const float*)d_in[9];
    float* out = (float*)d_out;

    void *pXh, *pXl, *pWh, *pWl, *pAh, *pAl, *pWoh, *pWol;
    cudaGetSymbolAddress(&pXh,  g_xh);
    cudaGetSymbolAddress(&pXl,  g_xl);
    cudaGetSymbolAddress(&pWh,  g_Wh);
    cudaGetSymbolAddress(&pWl,  g_Wl);
    cudaGetSymbolAddress(&pAh,  g_atth);
    cudaGetSymbolAddress(&pAl,  g_attl);
    cudaGetSymbolAddress(&pWoh, g_woh);
    cudaGetSymbolAddress(&pWol, g_wol);

    const int SMEM = 3 * 4 * 128 * 32 * 2;   // 98304 bytes (3 swizzled 32KB stages)
    cudaFuncSetAttribute(hgemm3, cudaFuncAttributeMaxDynamicSharedMemorySize, SMEM);
    const int SCAN_SMEM = (8192 + WPB*32*36 + WPB*2*8*2) * 4;   // 51712 bytes
    cudaFuncSetAttribute(scanOut, cudaFuncAttributeMaxDynamicSharedMemorySize, SCAN_SMEM);

    // 1) fused conversions: pack/split W, split x, split Wo
    cvtAll<<<10784, 256>>>(x, Wq, Wk, Wv, Ww, Wbeta, Wg, Wo);

    // 2) projection GEMM + activations, scattering straight into SoA streams (mode 1)
    hgemm3<<<dim3(NCP / 128, MROWS / 128), 256, SMEM>>>(
        (const __nv_bfloat16*)pXh, (const __nv_bfloat16*)pXl,
        (const __nv_bfloat16*)pWh, (const __nv_bfloat16*)pWl,
        nullptr, NC, HIDq, 1, bbeta, bg);

    // 3) chunked associative scan (w-normalization + eg scaling folded in)
    scanPA<<<(BH * CCH) / WPB, WPB * 32>>>();
    combine<<<BH, 1024>>>();
    scanOut<<<(BH * CCH) / WPB, WPB * 32, SCAN_SMEM>>>();

    // 4) output projection: out[16384,512] = att @ Wo^T (mode 0, row-major)
    hgemm3<<<dim3(HIDq / 128, MROWS / 128), 256, SMEM>>>(
        (const __nv_bfloat16*)pAh, (const __nv_bfloat16*)pAl,
        (const __nv_bfloat16*)pWoh, (const __nv_bfloat16*)pWol,
        out, HIDq, Hh * Dd, 0, nullptr, nullptr);
}